// round 14
// baseline (speedup 1.0000x reference)
#include <cuda_runtime.h>
#include <cuda_bf16.h>
#include <cuda_fp16.h>
#include <cstdint>
#include <math.h>

#define LSEQ 2048
#define DM   1024
#define DI   2048
#define DTR  64
#define NS   16
#define NPROJ 96   // dt_rank + 2N

// ---------------- scratch (static device allocations; no cudaMalloc) --------
__device__ __nv_bfloat16 g_hnormb[LSEQ * DM];     // rmsnorm out (bf16)
__device__ float g_h[LSEQ * 4 * DM];              // in-proj out [xs|res] fp32
__device__ float g_xs[LSEQ * DI];                 // fp32 (scan)
__device__ __nv_bfloat16 g_xsb[LSEQ * DI];        // bf16 (proj GEMM)
__device__ float g_res[LSEQ * DI];
__device__ float g_proj[LSEQ * NPROJ];            // [delta_low(64) | B(16) | C(16)]
__device__ float g_delta[LSEQ * DI];
__device__ __nv_bfloat16 g_ub[LSEQ * DI];         // scan out bf16
// K-major weights
__device__ __nv_bfloat16 g_w_inT[4 * DM * DM];
__device__ __nv_bfloat16 g_w_outT[DM * DI];
__device__ __nv_bfloat16 g_w_xprojT[128 * DI];
__device__ float g_w_dtT[DI * DTR];

__device__ __forceinline__ float siluf(float x) {
    return x / (1.0f + __expf(-x));
}
__device__ __forceinline__ uint32_t tf32r(float x) {
    uint32_t y;
    asm("cvt.rna.tf32.f32 %0, %1;" : "=r"(y) : "f"(x));
    return y;
}
__device__ __forceinline__ uint32_t smem_u32(const void* p) {
    uint32_t a;
    asm("{ .reg .u64 t; cvta.to.shared.u64 t, %1; cvt.u32.u64 %0, t; }"
        : "=r"(a) : "l"(p));
    return a;
}
__device__ __forceinline__ void ldm_x4(uint32_t& r0, uint32_t& r1,
                                       uint32_t& r2, uint32_t& r3, uint32_t addr) {
    asm volatile("ldmatrix.sync.aligned.m8n8.x4.shared.b16 {%0,%1,%2,%3}, [%4];"
                 : "=r"(r0), "=r"(r1), "=r"(r2), "=r"(r3) : "r"(addr));
}
__device__ __forceinline__ void cp16(uint32_t dst, const void* src) {
    asm volatile("cp.async.cg.shared.global [%0], [%1], 16;"
                 :: "r"(dst), "l"(src) : "memory");
}
__device__ __forceinline__ void cp_commit() {
    asm volatile("cp.async.commit_group;" ::: "memory");
}
__device__ __forceinline__ void cp_wait0() {
    asm volatile("cp.async.wait_group 0;" ::: "memory");
}

// ============ bf16 HMMA GEMM: 128x128 tile, 4 warps (2x2), 64x64/warp =======
// C[M,N] = A[M,K] @ B^T, both bf16 K-major.  cp.async double-buffer staging,
// ldmatrix fragment loads.  SMEM bytes/MAC ~2x lower than the 8-warp version.
// EPI 0: plain fp32  2: acc + X[row,col]  3: atomicAdd into C for cols < nstore
#define BSTH 40  // halfs per smem row (32 + 8 pad); 80B rows = 5x16B (cp.async-aligned)

template <int EPI>
__global__ void __launch_bounds__(128)
bgemm(int K, int lda, int ldb, int ldc, int nstore,
      const __nv_bfloat16* __restrict__ A, const __nv_bfloat16* __restrict__ B,
      const float* __restrict__ X, float* __restrict__ C) {
    __shared__ __nv_bfloat16 As[2][128 * BSTH];
    __shared__ __nv_bfloat16 Bs[2][128 * BSTH];
    int tid = threadIdx.x;
    int wid = tid >> 5, lane = tid & 31;
    int wm = wid & 1;        // 2 warps over M (64 rows each)
    int wn = wid >> 1;       // 2 warps over N (64 cols each)
    int g = lane >> 2, tg = lane & 3;

    const __nv_bfloat16* Ab = A + (size_t)(blockIdx.y * 128) * lda + (size_t)blockIdx.z * K;
    const __nv_bfloat16* Bb = B + (size_t)(blockIdx.x * 128) * ldb + (size_t)blockIdx.z * K;

    float c[4][8][4];
#pragma unroll
    for (int i = 0; i < 4; i++)
#pragma unroll
        for (int j = 0; j < 8; j++)
#pragma unroll
            for (int k = 0; k < 4; k++) c[i][j][k] = 0.f;

    const int S = K / 32;

    // ldmatrix per-lane byte offsets (within a buffer)
    uint32_t a_off = (((uint32_t)(wm * 64 + (lane & 15)) * BSTH) + 8u * (lane >> 4)) * 2u;
    uint32_t b_off = (((uint32_t)(wn * 64 + (lane & 7) + 8 * ((lane >> 3) >> 1)) * BSTH)
                      + 8u * ((lane >> 3) & 1)) * 2u;

    uint32_t sA0 = smem_u32(&As[0][0]);
    uint32_t sB0 = smem_u32(&Bs[0][0]);

    // cp.async staging: 128 threads, each loads one 64B row-chunk (4x16B) per operand
    auto issue_stage = [&](int s) {
        int buf = s & 1;
        int k0 = s * 32;
        const __nv_bfloat16* pa = Ab + (size_t)tid * lda + k0;
        const __nv_bfloat16* pb = Bb + (size_t)tid * ldb + k0;
        uint32_t da = sA0 + (uint32_t)buf * (128 * BSTH * 2) + (uint32_t)tid * BSTH * 2;
        uint32_t db = sB0 + (uint32_t)buf * (128 * BSTH * 2) + (uint32_t)tid * BSTH * 2;
#pragma unroll
        for (int q = 0; q < 4; q++) {
            cp16(da + q * 16, pa + q * 8);
            cp16(db + q * 16, pb + q * 8);
        }
    };

    issue_stage(0);
    cp_commit();

    for (int s = 0; s < S; s++) {
        cp_wait0();
        __syncthreads();
        if (s + 1 < S) {
            issue_stage(s + 1);
            cp_commit();
        }
        int buf = s & 1;
        uint32_t sA = sA0 + (uint32_t)buf * (128 * BSTH * 2);
        uint32_t sB = sB0 + (uint32_t)buf * (128 * BSTH * 2);
#pragma unroll
        for (int kk = 0; kk < 32; kk += 16) {
            uint32_t af[4][4], bf[8][2];
#pragma unroll
            for (int mt = 0; mt < 4; mt++)
                ldm_x4(af[mt][0], af[mt][1], af[mt][2], af[mt][3],
                       sA + a_off + (uint32_t)(mt * 16 * BSTH + kk) * 2u);
#pragma unroll
            for (int p = 0; p < 4; p++)
                ldm_x4(bf[2 * p][0], bf[2 * p][1], bf[2 * p + 1][0], bf[2 * p + 1][1],
                       sB + b_off + (uint32_t)(p * 16 * BSTH + kk) * 2u);
#pragma unroll
            for (int mt = 0; mt < 4; mt++)
#pragma unroll
                for (int nt = 0; nt < 8; nt++) {
                    asm volatile(
                        "mma.sync.aligned.m16n8k16.row.col.f32.bf16.bf16.f32 "
                        "{%0,%1,%2,%3}, {%4,%5,%6,%7}, {%8,%9}, {%0,%1,%2,%3};"
                        : "+f"(c[mt][nt][0]), "+f"(c[mt][nt][1]),
                          "+f"(c[mt][nt][2]), "+f"(c[mt][nt][3])
                        : "r"(af[mt][0]), "r"(af[mt][1]), "r"(af[mt][2]), "r"(af[mt][3]),
                          "r"(bf[nt][0]), "r"(bf[nt][1]));
                }
        }
        __syncthreads();
    }

#pragma unroll
    for (int mt = 0; mt < 4; mt++) {
        int row = blockIdx.y * 128 + wm * 64 + mt * 16 + g;
#pragma unroll
        for (int nt = 0; nt < 8; nt++) {
            int col = blockIdx.x * 128 + wn * 64 + nt * 8 + tg * 2;
#pragma unroll
            for (int h = 0; h < 2; h++) {
                int rr = row + h * 8;
                float v0 = c[mt][nt][h * 2 + 0];
                float v1 = c[mt][nt][h * 2 + 1];
                if (EPI == 2) {
                    v0 += X[(size_t)rr * ldc + col];
                    v1 += X[(size_t)rr * ldc + col + 1];
                }
                if (EPI == 3) {
                    if (col < nstore) {
                        atomicAdd(&C[(size_t)rr * ldc + col], v0);
                        atomicAdd(&C[(size_t)rr * ldc + col + 1], v1);
                    }
                } else {
                    *(float2*)&C[(size_t)rr * ldc + col] = make_float2(v0, v1);
                }
            }
        }
    }
}

// ============ tf32 HMMA GEMM (delta path only), BK=16 =======================
#define BK 16
#define SST 20

__global__ void __launch_bounds__(256)
mma_gemm_sp(int K, int lda, int ldb, int ldc,
            const float* __restrict__ A, const float* __restrict__ B,
            const float* __restrict__ X, float* __restrict__ C) {
    __shared__ uint32_t As[2][128 * SST];
    __shared__ uint32_t Bs[2][128 * SST];
    int tid = threadIdx.x;
    int wid = tid >> 5, lane = tid & 31;
    int wm = wid & 1, wn = wid >> 1;
    int g = lane >> 2, tg = lane & 3;

    const float* Ab = A + (size_t)(blockIdx.y * 128) * lda;
    const float* Bb = B + (size_t)(blockIdx.x * 128) * ldb;

    float c[4][4][4];
#pragma unroll
    for (int i = 0; i < 4; i++)
#pragma unroll
        for (int j = 0; j < 4; j++)
#pragma unroll
            for (int k = 0; k < 4; k++) c[i][j][k] = 0.f;

    const int S = K / BK;
    int r0 = tid >> 2, kq0 = tid & 3;
    int r1 = (tid + 256) >> 2, kq1 = tid & 3;

    {
        float4 a0v = *(const float4*)(Ab + (size_t)r0 * lda + kq0 * 4);
        float4 a1v = *(const float4*)(Ab + (size_t)r1 * lda + kq1 * 4);
        float4 b0v = *(const float4*)(Bb + (size_t)r0 * ldb + kq0 * 4);
        float4 b1v = *(const float4*)(Bb + (size_t)r1 * ldb + kq1 * 4);
        *(uint4*)&As[0][r0 * SST + kq0 * 4] =
            make_uint4(tf32r(a0v.x), tf32r(a0v.y), tf32r(a0v.z), tf32r(a0v.w));
        *(uint4*)&As[0][r1 * SST + kq1 * 4] =
            make_uint4(tf32r(a1v.x), tf32r(a1v.y), tf32r(a1v.z), tf32r(a1v.w));
        *(uint4*)&Bs[0][r0 * SST + kq0 * 4] =
            make_uint4(tf32r(b0v.x), tf32r(b0v.y), tf32r(b0v.z), tf32r(b0v.w));
        *(uint4*)&Bs[0][r1 * SST + kq1 * 4] =
            make_uint4(tf32r(b1v.x), tf32r(b1v.y), tf32r(b1v.z), tf32r(b1v.w));
    }
    __syncthreads();

    for (int s = 0; s < S; s++) {
        int buf = s & 1;
        float4 a0v, a1v, b0v, b1v;
        const bool more = (s + 1) < S;
        if (more) {
            int k0 = (s + 1) * BK;
            a0v = *(const float4*)(Ab + (size_t)r0 * lda + k0 + kq0 * 4);
            a1v = *(const float4*)(Ab + (size_t)r1 * lda + k0 + kq1 * 4);
            b0v = *(const float4*)(Bb + (size_t)r0 * ldb + k0 + kq0 * 4);
            b1v = *(const float4*)(Bb + (size_t)r1 * ldb + k0 + kq1 * 4);
        }
#pragma unroll
        for (int kk = 0; kk < BK; kk += 8) {
            uint32_t af[4][4], bf[4][2];
#pragma unroll
            for (int mt = 0; mt < 4; mt++) {
                const uint32_t* p = &As[buf][(wm * 64 + mt * 16 + g) * SST + kk + tg];
                af[mt][0] = p[0];
                af[mt][1] = p[8 * SST];
                af[mt][2] = p[4];
                af[mt][3] = p[8 * SST + 4];
            }
#pragma unroll
            for (int nt = 0; nt < 4; nt++) {
                const uint32_t* q = &Bs[buf][(wn * 32 + nt * 8 + g) * SST + kk + tg];
                bf[nt][0] = q[0];
                bf[nt][1] = q[4];
            }
#pragma unroll
            for (int mt = 0; mt < 4; mt++)
#pragma unroll
                for (int nt = 0; nt < 4; nt++) {
                    asm volatile(
                        "mma.sync.aligned.m16n8k8.row.col.f32.tf32.tf32.f32 "
                        "{%0,%1,%2,%3}, {%4,%5,%6,%7}, {%8,%9}, {%0,%1,%2,%3};"
                        : "+f"(c[mt][nt][0]), "+f"(c[mt][nt][1]),
                          "+f"(c[mt][nt][2]), "+f"(c[mt][nt][3])
                        : "r"(af[mt][0]), "r"(af[mt][1]), "r"(af[mt][2]), "r"(af[mt][3]),
                          "r"(bf[nt][0]), "r"(bf[nt][1]));
                }
        }
        if (more) {
            int nb = buf ^ 1;
            *(uint4*)&As[nb][r0 * SST + kq0 * 4] =
                make_uint4(tf32r(a0v.x), tf32r(a0v.y), tf32r(a0v.z), tf32r(a0v.w));
            *(uint4*)&As[nb][r1 * SST + kq1 * 4] =
                make_uint4(tf32r(a1v.x), tf32r(a1v.y), tf32r(a1v.z), tf32r(a1v.w));
            *(uint4*)&Bs[nb][r0 * SST + kq0 * 4] =
                make_uint4(tf32r(b0v.x), tf32r(b0v.y), tf32r(b0v.z), tf32r(b0v.w));
            *(uint4*)&Bs[nb][r1 * SST + kq1 * 4] =
                make_uint4(tf32r(b1v.x), tf32r(b1v.y), tf32r(b1v.z), tf32r(b1v.w));
        }
        __syncthreads();
    }

    // epilogue: softplus(acc + bias[col])
#pragma unroll
    for (int mt = 0; mt < 4; mt++) {
        int row = blockIdx.y * 128 + wm * 64 + mt * 16 + g;
#pragma unroll
        for (int nt = 0; nt < 4; nt++) {
            int col = blockIdx.x * 128 + wn * 32 + nt * 8 + tg * 2;
#pragma unroll
            for (int h = 0; h < 2; h++) {
                int rr = row + h * 8;
                float v0 = c[mt][nt][h * 2 + 0] + X[col];
                float v1 = c[mt][nt][h * 2 + 1] + X[col + 1];
                v0 = (v0 > 20.f) ? v0 : log1pf(__expf(v0));
                v1 = (v1 > 20.f) ? v1 : log1pf(__expf(v1));
                *(float2*)&C[(size_t)rr * ldc + col] = make_float2(v0, v1);
            }
        }
    }
}

// ---------------- weight transposes ------------------------------------------
__global__ void transpose_bf(const float* __restrict__ in, __nv_bfloat16* __restrict__ out,
                             int K, int N, int NOUT) {
    __shared__ float t[32][33];
    int kb = blockIdx.x * 32, nb = blockIdx.y * 32;
    int tx = threadIdx.x, ty = threadIdx.y;  // 32 x 8
#pragma unroll
    for (int i = 0; i < 32; i += 8) {
        int k = kb + ty + i, n = nb + tx;
        t[ty + i][tx] = (n < N) ? in[(size_t)k * N + n] : 0.f;
    }
    __syncthreads();
#pragma unroll
    for (int i = 0; i < 32; i += 8) {
        int n = nb + ty + i, k = kb + tx;
        if (n < NOUT) out[(size_t)n * K + k] = __float2bfloat16_rn(t[tx][ty + i]);
    }
}
__global__ void transpose_f32(const float* __restrict__ in, float* __restrict__ out,
                              int K, int N) {
    __shared__ float t[32][33];
    int kb = blockIdx.x * 32, nb = blockIdx.y * 32;
    int tx = threadIdx.x, ty = threadIdx.y;
#pragma unroll
    for (int i = 0; i < 32; i += 8)
        t[ty + i][tx] = in[(size_t)(kb + ty + i) * N + nb + tx];
    __syncthreads();
#pragma unroll
    for (int i = 0; i < 32; i += 8)
        out[(size_t)(nb + ty + i) * K + kb + tx] = t[tx][ty + i];
}

__global__ void zero_proj_k() {
    int i = blockIdx.x * 256 + threadIdx.x;
    ((float4*)g_proj)[i] = make_float4(0.f, 0.f, 0.f, 0.f);
}

// ---------------- RMSNorm (writes bf16) -------------------------------------
__global__ void rmsnorm_k(const float* __restrict__ x,
                          const float* __restrict__ sc) {
    int row = blockIdx.x;
    int t = threadIdx.x;
    float4 v = ((const float4*)(x + (size_t)row * DM))[t];
    float s = v.x * v.x + v.y * v.y + v.z * v.z + v.w * v.w;
#pragma unroll
    for (int o = 16; o; o >>= 1) s += __shfl_xor_sync(0xffffffffu, s, o);
    __shared__ float red[8];
    if ((t & 31) == 0) red[t >> 5] = s;
    __syncthreads();
    float tot = 0.f;
#pragma unroll
    for (int i = 0; i < 8; i++) tot += red[i];
    float inv = rsqrtf(tot * (1.0f / DM) + 1e-5f);
    float4 gsc = ((const float4*)sc)[t];
    __nv_bfloat162 p0, p1;
    p0.x = __float2bfloat16_rn(v.x * inv * gsc.x);
    p0.y = __float2bfloat16_rn(v.y * inv * gsc.y);
    p1.x = __float2bfloat16_rn(v.z * inv * gsc.z);
    p1.y = __float2bfloat16_rn(v.w * inv * gsc.w);
    ((__nv_bfloat162*)(g_hnormb + (size_t)row * DM))[t * 2] = p0;
    ((__nv_bfloat162*)(g_hnormb + (size_t)row * DM))[t * 2 + 1] = p1;
}

// ---------------- causal depthwise conv (K=4) + silu ------------------------
__global__ void conv_silu_k(const float* __restrict__ cw,
                            const float* __restrict__ cb) {
    int idx = blockIdx.x * 256 + threadIdx.x;
    int c = idx & (DI - 1);
    int l = idx >> 11;
    float acc = cb[c];
#pragma unroll
    for (int k = 0; k < 4; k++) {
        int ls = l - 3 + k;
        if (ls >= 0) acc = fmaf(g_h[(size_t)ls * (4 * DM) + c], cw[k * DI + c], acc);
    }
    float xs = siluf(acc);
    g_xs[idx] = xs;
    g_xsb[idx] = __float2bfloat16_rn(xs);
    float r = g_h[(size_t)l * (4 * DM) + DI + c];
    g_res[idx] = siluf(r);
}

// ---------------- selective scan: fp16x2 exp2, 2 timesteps per MUFU op ------
__global__ void __launch_bounds__(256) scan_k(const float* __restrict__ A_log,
                                              const float* __restrict__ Dp) {
    int lane = threadIdx.x & 31;
    int n = lane & 15;
    int half = lane >> 4;
    int warp = threadIdx.x >> 5;
    int c = blockIdx.x * 16 + warp * 2 + half;

    float Ah = -__expf(A_log[c * NS + n]) * 1.44269504f;  // log2(e) folded
    float Dc = Dp[c];
    float state = 0.f;

    const float* dlt = g_delta + c;
    const float* xsp = g_xs + c;
    const float* rsp = g_res + c;
    __nv_bfloat16* up = g_ub + c;

#pragma unroll 2
    for (int l = 0; l < LSEQ; l += 2) {
        float d0 = dlt[(size_t)l * DI];
        float d1 = dlt[(size_t)(l + 1) * DI];
        float x0 = xsp[(size_t)l * DI];
        float x1 = xsp[(size_t)(l + 1) * DI];
        float B0 = g_proj[(size_t)l * NPROJ + DTR + n];
        float B1 = g_proj[(size_t)(l + 1) * NPROJ + DTR + n];
        float C0 = g_proj[(size_t)l * NPROJ + DTR + NS + n];
        float C1 = g_proj[(size_t)(l + 1) * NPROJ + DTR + NS + n];

        __half2 hh = h2exp2(__floats2half2_rn(d0 * Ah, d1 * Ah));
        float dA0 = __low2float(hh);
        float dA1 = __high2float(hh);

        state = fmaf(dA0, state, d0 * x0 * B0);
        float y0 = state * C0;
        state = fmaf(dA1, state, d1 * x1 * B1);
        float y1 = state * C1;

        y0 += __shfl_xor_sync(0xffffffffu, y0, 1);
        y1 += __shfl_xor_sync(0xffffffffu, y1, 1);
        y0 += __shfl_xor_sync(0xffffffffu, y0, 2);
        y1 += __shfl_xor_sync(0xffffffffu, y1, 2);
        y0 += __shfl_xor_sync(0xffffffffu, y0, 4);
        y1 += __shfl_xor_sync(0xffffffffu, y1, 4);
        y0 += __shfl_xor_sync(0xffffffffu, y0, 8);
        y1 += __shfl_xor_sync(0xffffffffu, y1, 8);

        if (n == 0) {
            float r0 = rsp[(size_t)l * DI];
            float r1 = rsp[(size_t)(l + 1) * DI];
            up[(size_t)l * DI] = __float2bfloat16_rn(fmaf(x0, Dc, y0) * r0);
            up[(size_t)(l + 1) * DI] = __float2bfloat16_rn(fmaf(x1, Dc, y1) * r1);
        }
    }
}

// ---------------- launch ----------------------------------------------------
extern "C" void kernel_launch(void* const* d_in, const int* in_sizes, int n_in,
                              void* d_out, int out_size) {
    const float* x          = (const float*)d_in[0];
    const float* norm_scale = (const float*)d_in[1];
    const float* w_in       = (const float*)d_in[2];
    const float* conv_w     = (const float*)d_in[3];
    const float* conv_b     = (const float*)d_in[4];
    const float* A_log      = (const float*)d_in[5];
    const float* Dv         = (const float*)d_in[6];
    const float* w_xproj    = (const float*)d_in[7];
    const float* w_dt       = (const float*)d_in[8];
    const float* b_dt       = (const float*)d_in[9];
    const float* w_out      = (const float*)d_in[10];

    __nv_bfloat16 *hnormb, *xsb, *ub, *w_inT, *w_outT, *w_xprojT;
    float *h, *proj, *delta, *w_dtT;
    cudaGetSymbolAddress((void**)&hnormb, g_hnormb);
    cudaGetSymbolAddress((void**)&h, g_h);
    cudaGetSymbolAddress((void**)&xsb, g_xsb);
    cudaGetSymbolAddress((void**)&proj, g_proj);
    cudaGetSymbolAddress((void**)&delta, g_delta);
    cudaGetSymbolAddress((void**)&ub, g_ub);
    cudaGetSymbolAddress((void**)&w_inT, g_w_inT);
    cudaGetSymbolAddress((void**)&w_outT, g_w_outT);
    cudaGetSymbolAddress((void**)&w_xprojT, g_w_xprojT);
    cudaGetSymbolAddress((void**)&w_dtT, g_w_dtT);

    dim3 t32x8(32, 8);
    // 0
    transpose_bf<<<dim3(DM / 32, 4 * DM / 32), t32x8>>>(w_in, w_inT, DM, 4 * DM, 4 * DM);
    // 1
    rmsnorm_k<<<LSEQ, 256>>>(x, norm_scale);
    // 2
    zero_proj_k<<<LSEQ * NPROJ / 4 / 256, 256>>>();
    // 3 (ncu capture slot): h = hnorm @ w_in  (2048 x 4096 x 1024), fp32 out
    bgemm<0><<<dim3(4 * DM / 128, LSEQ / 128), 128>>>(
        DM, DM, DM, 4 * DM, 4 * DM, hnormb, w_inT, nullptr, h);
    // 4-6
    transpose_bf<<<dim3(DI / 32, DM / 32), t32x8>>>(w_out, w_outT, DI, DM, DM);
    transpose_bf<<<dim3(DI / 32, 128 / 32), t32x8>>>(w_xproj, w_xprojT, DI, NPROJ, 128);
    transpose_f32<<<dim3(DTR / 32, DI / 32), t32x8>>>(w_dt, w_dtT, DTR, DI);
    // 7
    conv_silu_k<<<LSEQ * DI / 256, 256>>>(conv_w, conv_b);
    // 8: proj = xs @ w_xproj  (2048 x 96[pad128] x 2048), split-K=8
    bgemm<3><<<dim3(1, LSEQ / 128, 8), 128>>>(
        DI / 8, DI, DI, NPROJ, NPROJ, xsb, w_xprojT, nullptr, proj);
    // 9: delta = softplus(proj[:, :64] @ w_dt + b_dt)  (tf32)
    mma_gemm_sp<<<dim3(DI / 128, LSEQ / 128), 256>>>(
        DTR, NPROJ, DTR, DI, proj, w_dtT, b_dt, delta);
    // 10: selective scan
    scan_k<<<DI / 16, 256>>>(A_log, Dv);
    // 11: out = x + u @ w_out  (2048 x 1024 x 2048)
    bgemm<2><<<dim3(DM / 128, LSEQ / 128), 128>>>(
        DI, DI, DI, DM, DM, ub, w_outT, x, (float*)d_out);
}

// round 15
// speedup vs baseline: 2.1231x; 2.1231x over previous
#include <cuda_runtime.h>
#include <cuda_bf16.h>
#include <cuda_fp16.h>
#include <cstdint>
#include <math.h>

#define LSEQ 2048
#define DM   1024
#define DI   2048
#define DTR  64
#define NS   16
#define NPROJ 96   // dt_rank + 2N

// ---------------- scratch (static device allocations; no cudaMalloc) --------
__device__ __nv_bfloat16 g_hnormb[LSEQ * DM];     // rmsnorm out (bf16)
__device__ __nv_bfloat16 g_hb[LSEQ * 4 * DM];     // in-proj out [xs|res] bf16
__device__ __nv_bfloat16 g_xsb[LSEQ * DI];        // silu(conv) bf16 row-major
__device__ __nv_bfloat16 g_xsT[DI * LSEQ];        // xs channel-major
__device__ __nv_bfloat16 g_resT[DI * LSEQ];       // silu(res) channel-major
__device__ float g_proj[LSEQ * NPROJ];            // [delta_low(64) | B(16) | C(16)]
__device__ float g_delta[LSEQ * DI];              // softplus out fp32 row-major
__device__ __nv_bfloat16 g_deltaT[DI * LSEQ];     // delta channel-major bf16
__device__ __nv_bfloat16 g_ub[LSEQ * DI];         // scan out bf16 row-major
// K-major weights
__device__ __nv_bfloat16 g_w_inT[4 * DM * DM];
__device__ __nv_bfloat16 g_w_outT[DM * DI];
__device__ __nv_bfloat16 g_w_xprojT[128 * DI];
__device__ float g_w_dtT[DI * DTR];

__device__ __forceinline__ float siluf(float x) {
    return x / (1.0f + __expf(-x));
}
__device__ __forceinline__ uint32_t tf32r(float x) {
    uint32_t y;
    asm("cvt.rna.tf32.f32 %0, %1;" : "=r"(y) : "f"(x));
    return y;
}
__device__ __forceinline__ uint32_t smem_u32(const void* p) {
    uint32_t a;
    asm("{ .reg .u64 t; cvta.to.shared.u64 t, %1; cvt.u32.u64 %0, t; }"
        : "=r"(a) : "l"(p));
    return a;
}
__device__ __forceinline__ void ldm_x4(uint32_t& r0, uint32_t& r1,
                                       uint32_t& r2, uint32_t& r3, uint32_t addr) {
    asm volatile("ldmatrix.sync.aligned.m8n8.x4.shared.b16 {%0,%1,%2,%3}, [%4];"
                 : "=r"(r0), "=r"(r1), "=r"(r2), "=r"(r3) : "r"(addr));
}
__device__ __forceinline__ float2 bf2_to_f2(uint32_t u) {
    __nv_bfloat162 b;
    memcpy(&b, &u, 4);
    return __bfloat1622float2(b);
}

// ============ bf16 HMMA GEMM: 128x128 tile, BK=32, 8 warps (2x4) ============
// R11-proven structure: reg-staged double buffer + ldmatrix fragment loads.
// EPI 0: store bf16  2: fp32 acc + X[row,col]  3: atomicAdd fp32 cols < nstore
#define BSTH 40  // halfs per smem row (32 + 8 pad)

template <int EPI>
__global__ void __launch_bounds__(256)
bgemm(int K, int lda, int ldb, int ldc, int nstore,
      const __nv_bfloat16* __restrict__ A, const __nv_bfloat16* __restrict__ B,
      const float* __restrict__ X, void* __restrict__ Cout) {
    __shared__ __nv_bfloat16 As[2][128 * BSTH];
    __shared__ __nv_bfloat16 Bs[2][128 * BSTH];
    int tid = threadIdx.x;
    int wid = tid >> 5, lane = tid & 31;
    int wm = wid & 1;        // 2 warps over M (64 rows each)
    int wn = wid >> 1;       // 4 warps over N (32 cols each)
    int g = lane >> 2, tg = lane & 3;

    const __nv_bfloat16* Ab = A + (size_t)(blockIdx.y * 128) * lda + (size_t)blockIdx.z * K;
    const __nv_bfloat16* Bb = B + (size_t)(blockIdx.x * 128) * ldb + (size_t)blockIdx.z * K;

    float c[4][4][4];
#pragma unroll
    for (int i = 0; i < 4; i++)
#pragma unroll
        for (int j = 0; j < 4; j++)
#pragma unroll
            for (int k = 0; k < 4; k++) c[i][j][k] = 0.f;

    const int S = K / 32;
    int r = tid >> 1;            // 0..127
    int hb = (tid & 1) * 16;     // col-half (16 bf16 = 32B)

    uint32_t a_off = (((uint32_t)(wm * 64 + (lane & 15)) * BSTH) + 8u * (lane >> 4)) * 2u;
    uint32_t b_off = (((uint32_t)(wn * 32 + (lane & 7) + 8 * ((lane >> 3) >> 1)) * BSTH)
                      + 8u * ((lane >> 3) & 1)) * 2u;

    // prologue -> buf 0
    {
        const __nv_bfloat16* pa = Ab + (size_t)r * lda + hb;
        const __nv_bfloat16* pb = Bb + (size_t)r * ldb + hb;
        *(uint4*)&As[0][r * BSTH + hb]     = *(const uint4*)pa;
        *(uint4*)&As[0][r * BSTH + hb + 8] = *(const uint4*)(pa + 8);
        *(uint4*)&Bs[0][r * BSTH + hb]     = *(const uint4*)pb;
        *(uint4*)&Bs[0][r * BSTH + hb + 8] = *(const uint4*)(pb + 8);
    }
    __syncthreads();

    for (int s = 0; s < S; s++) {
        int buf = s & 1;
        uint4 va0, va1, vb0, vb1;
        const bool more = (s + 1) < S;
        if (more) {
            const __nv_bfloat16* pa = Ab + (size_t)r * lda + (s + 1) * 32 + hb;
            const __nv_bfloat16* pb = Bb + (size_t)r * ldb + (s + 1) * 32 + hb;
            va0 = *(const uint4*)pa;
            va1 = *(const uint4*)(pa + 8);
            vb0 = *(const uint4*)pb;
            vb1 = *(const uint4*)(pb + 8);
        }
        uint32_t sA = smem_u32(&As[buf][0]);
        uint32_t sB = smem_u32(&Bs[buf][0]);
#pragma unroll
        for (int kk = 0; kk < 32; kk += 16) {
            uint32_t af[4][4], bf[4][2];
#pragma unroll
            for (int mt = 0; mt < 4; mt++)
                ldm_x4(af[mt][0], af[mt][1], af[mt][2], af[mt][3],
                       sA + a_off + (uint32_t)(mt * 16 * BSTH + kk) * 2u);
#pragma unroll
            for (int p = 0; p < 2; p++)
                ldm_x4(bf[2 * p][0], bf[2 * p][1], bf[2 * p + 1][0], bf[2 * p + 1][1],
                       sB + b_off + (uint32_t)(p * 16 * BSTH + kk) * 2u);
#pragma unroll
            for (int mt = 0; mt < 4; mt++)
#pragma unroll
                for (int nt = 0; nt < 4; nt++) {
                    asm volatile(
                        "mma.sync.aligned.m16n8k16.row.col.f32.bf16.bf16.f32 "
                        "{%0,%1,%2,%3}, {%4,%5,%6,%7}, {%8,%9}, {%0,%1,%2,%3};"
                        : "+f"(c[mt][nt][0]), "+f"(c[mt][nt][1]),
                          "+f"(c[mt][nt][2]), "+f"(c[mt][nt][3])
                        : "r"(af[mt][0]), "r"(af[mt][1]), "r"(af[mt][2]), "r"(af[mt][3]),
                          "r"(bf[nt][0]), "r"(bf[nt][1]));
                }
        }
        if (more) {
            int nb = buf ^ 1;
            *(uint4*)&As[nb][r * BSTH + hb]     = va0;
            *(uint4*)&As[nb][r * BSTH + hb + 8] = va1;
            *(uint4*)&Bs[nb][r * BSTH + hb]     = vb0;
            *(uint4*)&Bs[nb][r * BSTH + hb + 8] = vb1;
        }
        __syncthreads();
    }

#pragma unroll
    for (int mt = 0; mt < 4; mt++) {
        int row = blockIdx.y * 128 + wm * 64 + mt * 16 + g;
#pragma unroll
        for (int nt = 0; nt < 4; nt++) {
            int col = blockIdx.x * 128 + wn * 32 + nt * 8 + tg * 2;
#pragma unroll
            for (int h = 0; h < 2; h++) {
                int rr = row + h * 8;
                float v0 = c[mt][nt][h * 2 + 0];
                float v1 = c[mt][nt][h * 2 + 1];
                if (EPI == 0) {
                    __nv_bfloat162 st;
                    st.x = __float2bfloat16_rn(v0);
                    st.y = __float2bfloat16_rn(v1);
                    *(__nv_bfloat162*)&((__nv_bfloat16*)Cout)[(size_t)rr * ldc + col] = st;
                } else if (EPI == 2) {
                    v0 += X[(size_t)rr * ldc + col];
                    v1 += X[(size_t)rr * ldc + col + 1];
                    *(float2*)&((float*)Cout)[(size_t)rr * ldc + col] = make_float2(v0, v1);
                } else {  // EPI == 3
                    if (col < nstore) {
                        atomicAdd(&((float*)Cout)[(size_t)rr * ldc + col], v0);
                        atomicAdd(&((float*)Cout)[(size_t)rr * ldc + col + 1], v1);
                    }
                }
            }
        }
    }
}

// ============ tf32 HMMA GEMM (delta path only), BK=16 =======================
#define BK 16
#define SST 20

__global__ void __launch_bounds__(256)
mma_gemm_sp(int K, int lda, int ldb, int ldc,
            const float* __restrict__ A, const float* __restrict__ B,
            const float* __restrict__ X, float* __restrict__ C) {
    __shared__ uint32_t As[2][128 * SST];
    __shared__ uint32_t Bs[2][128 * SST];
    int tid = threadIdx.x;
    int wid = tid >> 5, lane = tid & 31;
    int wm = wid & 1, wn = wid >> 1;
    int g = lane >> 2, tg = lane & 3;

    const float* Ab = A + (size_t)(blockIdx.y * 128) * lda;
    const float* Bb = B + (size_t)(blockIdx.x * 128) * ldb;

    float c[4][4][4];
#pragma unroll
    for (int i = 0; i < 4; i++)
#pragma unroll
        for (int j = 0; j < 4; j++)
#pragma unroll
            for (int k = 0; k < 4; k++) c[i][j][k] = 0.f;

    const int S = K / BK;
    int r0 = tid >> 2, kq0 = tid & 3;
    int r1 = (tid + 256) >> 2, kq1 = tid & 3;

    {
        float4 a0v = *(const float4*)(Ab + (size_t)r0 * lda + kq0 * 4);
        float4 a1v = *(const float4*)(Ab + (size_t)r1 * lda + kq1 * 4);
        float4 b0v = *(const float4*)(Bb + (size_t)r0 * ldb + kq0 * 4);
        float4 b1v = *(const float4*)(Bb + (size_t)r1 * ldb + kq1 * 4);
        *(uint4*)&As[0][r0 * SST + kq0 * 4] =
            make_uint4(tf32r(a0v.x), tf32r(a0v.y), tf32r(a0v.z), tf32r(a0v.w));
        *(uint4*)&As[0][r1 * SST + kq1 * 4] =
            make_uint4(tf32r(a1v.x), tf32r(a1v.y), tf32r(a1v.z), tf32r(a1v.w));
        *(uint4*)&Bs[0][r0 * SST + kq0 * 4] =
            make_uint4(tf32r(b0v.x), tf32r(b0v.y), tf32r(b0v.z), tf32r(b0v.w));
        *(uint4*)&Bs[0][r1 * SST + kq1 * 4] =
            make_uint4(tf32r(b1v.x), tf32r(b1v.y), tf32r(b1v.z), tf32r(b1v.w));
    }
    __syncthreads();

    for (int s = 0; s < S; s++) {
        int buf = s & 1;
        float4 a0v, a1v, b0v, b1v;
        const bool more = (s + 1) < S;
        if (more) {
            int k0 = (s + 1) * BK;
            a0v = *(const float4*)(Ab + (size_t)r0 * lda + k0 + kq0 * 4);
            a1v = *(const float4*)(Ab + (size_t)r1 * lda + k0 + kq1 * 4);
            b0v = *(const float4*)(Bb + (size_t)r0 * ldb + k0 + kq0 * 4);
            b1v = *(const float4*)(Bb + (size_t)r1 * ldb + k0 + kq1 * 4);
        }
#pragma unroll
        for (int kk = 0; kk < BK; kk += 8) {
            uint32_t af[4][4], bf[4][2];
#pragma unroll
            for (int mt = 0; mt < 4; mt++) {
                const uint32_t* p = &As[buf][(wm * 64 + mt * 16 + g) * SST + kk + tg];
                af[mt][0] = p[0];
                af[mt][1] = p[8 * SST];
                af[mt][2] = p[4];
                af[mt][3] = p[8 * SST + 4];
            }
#pragma unroll
            for (int nt = 0; nt < 4; nt++) {
                const uint32_t* q = &Bs[buf][(wn * 32 + nt * 8 + g) * SST + kk + tg];
                bf[nt][0] = q[0];
                bf[nt][1] = q[4];
            }
#pragma unroll
            for (int mt = 0; mt < 4; mt++)
#pragma unroll
                for (int nt = 0; nt < 4; nt++) {
                    asm volatile(
                        "mma.sync.aligned.m16n8k8.row.col.f32.tf32.tf32.f32 "
                        "{%0,%1,%2,%3}, {%4,%5,%6,%7}, {%8,%9}, {%0,%1,%2,%3};"
                        : "+f"(c[mt][nt][0]), "+f"(c[mt][nt][1]),
                          "+f"(c[mt][nt][2]), "+f"(c[mt][nt][3])
                        : "r"(af[mt][0]), "r"(af[mt][1]), "r"(af[mt][2]), "r"(af[mt][3]),
                          "r"(bf[nt][0]), "r"(bf[nt][1]));
                }
        }
        if (more) {
            int nb = buf ^ 1;
            *(uint4*)&As[nb][r0 * SST + kq0 * 4] =
                make_uint4(tf32r(a0v.x), tf32r(a0v.y), tf32r(a0v.z), tf32r(a0v.w));
            *(uint4*)&As[nb][r1 * SST + kq1 * 4] =
                make_uint4(tf32r(a1v.x), tf32r(a1v.y), tf32r(a1v.z), tf32r(a1v.w));
            *(uint4*)&Bs[nb][r0 * SST + kq0 * 4] =
                make_uint4(tf32r(b0v.x), tf32r(b0v.y), tf32r(b0v.z), tf32r(b0v.w));
            *(uint4*)&Bs[nb][r1 * SST + kq1 * 4] =
                make_uint4(tf32r(b1v.x), tf32r(b1v.y), tf32r(b1v.z), tf32r(b1v.w));
        }
        __syncthreads();
    }

    // epilogue: softplus(acc + bias[col])
#pragma unroll
    for (int mt = 0; mt < 4; mt++) {
        int row = blockIdx.y * 128 + wm * 64 + mt * 16 + g;
#pragma unroll
        for (int nt = 0; nt < 4; nt++) {
            int col = blockIdx.x * 128 + wn * 32 + nt * 8 + tg * 2;
#pragma unroll
            for (int h = 0; h < 2; h++) {
                int rr = row + h * 8;
                float v0 = c[mt][nt][h * 2 + 0] + X[col];
                float v1 = c[mt][nt][h * 2 + 1] + X[col + 1];
                v0 = (v0 > 20.f) ? v0 : log1pf(__expf(v0));
                v1 = (v1 > 20.f) ? v1 : log1pf(__expf(v1));
                *(float2*)&C[(size_t)rr * ldc + col] = make_float2(v0, v1);
            }
        }
    }
}

// ---------------- weight transposes ------------------------------------------
__global__ void transpose_bf(const float* __restrict__ in, __nv_bfloat16* __restrict__ out,
                             int K, int N, int NOUT) {
    __shared__ float t[32][33];
    int kb = blockIdx.x * 32, nb = blockIdx.y * 32;
    int tx = threadIdx.x, ty = threadIdx.y;  // 32 x 8
#pragma unroll
    for (int i = 0; i < 32; i += 8) {
        int k = kb + ty + i, n = nb + tx;
        t[ty + i][tx] = (n < N) ? in[(size_t)k * N + n] : 0.f;
    }
    __syncthreads();
#pragma unroll
    for (int i = 0; i < 32; i += 8) {
        int n = nb + ty + i, k = kb + tx;
        if (n < NOUT) out[(size_t)n * K + k] = __float2bfloat16_rn(t[tx][ty + i]);
    }
}
__global__ void transpose_f32(const float* __restrict__ in, float* __restrict__ out,
                              int K, int N) {
    __shared__ float t[32][33];
    int kb = blockIdx.x * 32, nb = blockIdx.y * 32;
    int tx = threadIdx.x, ty = threadIdx.y;
#pragma unroll
    for (int i = 0; i < 32; i += 8)
        t[ty + i][tx] = in[(size_t)(kb + ty + i) * N + nb + tx];
    __syncthreads();
#pragma unroll
    for (int i = 0; i < 32; i += 8)
        out[(size_t)(nb + ty + i) * K + kb + tx] = t[tx][ty + i];
}

// data transposes (row-major [R, Cld] slice -> channel-major [Csub, R] bf16)
// SILU=1 applies silu on the fly (for res from h).
template <int SILU>
__global__ void transpose_bb(const __nv_bfloat16* __restrict__ in,
                             __nv_bfloat16* __restrict__ out,
                             int R, int Cld, int c_off) {
    __shared__ float t[32][33];
    int rb = blockIdx.x * 32, cb = blockIdx.y * 32;
    int tx = threadIdx.x, ty = threadIdx.y;  // 32 x 8
#pragma unroll
    for (int i = 0; i < 32; i += 8) {
        float v = __bfloat162float(in[(size_t)(rb + ty + i) * Cld + c_off + cb + tx]);
        t[ty + i][tx] = SILU ? siluf(v) : v;
    }
    __syncthreads();
#pragma unroll
    for (int i = 0; i < 32; i += 8)
        out[(size_t)(cb + ty + i) * R + rb + tx] = __float2bfloat16_rn(t[tx][ty + i]);
}
__global__ void transpose_f2b(const float* __restrict__ in,
                              __nv_bfloat16* __restrict__ out, int R, int C) {
    __shared__ float t[32][33];
    int rb = blockIdx.x * 32, cb = blockIdx.y * 32;
    int tx = threadIdx.x, ty = threadIdx.y;
#pragma unroll
    for (int i = 0; i < 32; i += 8)
        t[ty + i][tx] = in[(size_t)(rb + ty + i) * C + cb + tx];
    __syncthreads();
#pragma unroll
    for (int i = 0; i < 32; i += 8)
        out[(size_t)(cb + ty + i) * R + rb + tx] = __float2bfloat16_rn(t[tx][ty + i]);
}

__global__ void zero_proj_k() {
    int i = blockIdx.x * 256 + threadIdx.x;
    ((float4*)g_proj)[i] = make_float4(0.f, 0.f, 0.f, 0.f);
}

// ---------------- RMSNorm (writes bf16) -------------------------------------
__global__ void rmsnorm_k(const float* __restrict__ x,
                          const float* __restrict__ sc) {
    int row = blockIdx.x;
    int t = threadIdx.x;
    float4 v = ((const float4*)(x + (size_t)row * DM))[t];
    float s = v.x * v.x + v.y * v.y + v.z * v.z + v.w * v.w;
#pragma unroll
    for (int o = 16; o; o >>= 1) s += __shfl_xor_sync(0xffffffffu, s, o);
    __shared__ float red[8];
    if ((t & 31) == 0) red[t >> 5] = s;
    __syncthreads();
    float tot = 0.f;
#pragma unroll
    for (int i = 0; i < 8; i++) tot += red[i];
    float inv = rsqrtf(tot * (1.0f / DM) + 1e-5f);
    float4 gsc = ((const float4*)sc)[t];
    __nv_bfloat162 p0, p1;
    p0.x = __float2bfloat16_rn(v.x * inv * gsc.x);
    p0.y = __float2bfloat16_rn(v.y * inv * gsc.y);
    p1.x = __float2bfloat16_rn(v.z * inv * gsc.z);
    p1.y = __float2bfloat16_rn(v.w * inv * gsc.w);
    ((__nv_bfloat162*)(g_hnormb + (size_t)row * DM))[t * 2] = p0;
    ((__nv_bfloat162*)(g_hnormb + (size_t)row * DM))[t * 2 + 1] = p1;
}

// ---------------- causal depthwise conv (K=4) + silu (bf16 in/out) ----------
__global__ void conv_silu_k(const float* __restrict__ cw,
                            const float* __restrict__ cb) {
    int idx = blockIdx.x * 256 + threadIdx.x;
    int c = idx & (DI - 1);
    int l = idx >> 11;
    float acc = cb[c];
#pragma unroll
    for (int k = 0; k < 4; k++) {
        int ls = l - 3 + k;
        if (ls >= 0)
            acc = fmaf(__bfloat162float(g_hb[(size_t)ls * (4 * DM) + c]),
                       cw[k * DI + c], acc);
    }
    g_xsb[idx] = __float2bfloat16_rn(siluf(acc));
}

// ---------------- selective scan v2: channel-major broadcast loads ----------
__global__ void __launch_bounds__(256) scan2_k(const float* __restrict__ A_log,
                                               const float* __restrict__ Dp) {
    int lane = threadIdx.x & 31;
    int n = lane & 15;
    int half = lane >> 4;
    int warp = threadIdx.x >> 5;
    int c = blockIdx.x * 16 + warp * 2 + half;

    float Ah = -__expf(A_log[c * NS + n]) * 1.44269504f;  // log2(e) folded
    float Dc = Dp[c];
    float state = 0.f;

    const __nv_bfloat16* dT = g_deltaT + (size_t)c * LSEQ;
    const __nv_bfloat16* xT = g_xsT + (size_t)c * LSEQ;
    const __nv_bfloat16* rT = g_resT + (size_t)c * LSEQ;
    __nv_bfloat16* up = g_ub + c;

    for (int l = 0; l < LSEQ; l += 8) {
        // broadcast loads: 8 timesteps per uint4, all lanes of a channel same addr
        uint4 dv = *(const uint4*)(dT + l);
        uint4 xv = *(const uint4*)(xT + l);
        uint4 rv = *(const uint4*)(rT + l);
        float d[8], xf[8], rf[8];
        {
            float2 f;
            f = bf2_to_f2(dv.x); d[0] = f.x; d[1] = f.y;
            f = bf2_to_f2(dv.y); d[2] = f.x; d[3] = f.y;
            f = bf2_to_f2(dv.z); d[4] = f.x; d[5] = f.y;
            f = bf2_to_f2(dv.w); d[6] = f.x; d[7] = f.y;
            f = bf2_to_f2(xv.x); xf[0] = f.x; xf[1] = f.y;
            f = bf2_to_f2(xv.y); xf[2] = f.x; xf[3] = f.y;
            f = bf2_to_f2(xv.z); xf[4] = f.x; xf[5] = f.y;
            f = bf2_to_f2(xv.w); xf[6] = f.x; xf[7] = f.y;
            f = bf2_to_f2(rv.x); rf[0] = f.x; rf[1] = f.y;
            f = bf2_to_f2(rv.y); rf[2] = f.x; rf[3] = f.y;
            f = bf2_to_f2(rv.z); rf[4] = f.x; rf[5] = f.y;
            f = bf2_to_f2(rv.w); rf[6] = f.x; rf[7] = f.y;
        }
        float Bv[8], Cv[8];
#pragma unroll
        for (int j = 0; j < 8; j++) {
            Bv[j] = g_proj[(size_t)(l + j) * NPROJ + DTR + n];
            Cv[j] = g_proj[(size_t)(l + j) * NPROJ + DTR + NS + n];
        }
        float dA[8];
#pragma unroll
        for (int j = 0; j < 8; j += 2) {
            __half2 hh = h2exp2(__floats2half2_rn(d[j] * Ah, d[j + 1] * Ah));
            dA[j] = __low2float(hh);
            dA[j + 1] = __high2float(hh);
        }
        float y[8];
#pragma unroll
        for (int j = 0; j < 8; j++) {
            state = fmaf(dA[j], state, d[j] * xf[j] * Bv[j]);
            y[j] = state * Cv[j];
        }
#pragma unroll
        for (int j = 0; j < 8; j++) {
            y[j] += __shfl_xor_sync(0xffffffffu, y[j], 1);
            y[j] += __shfl_xor_sync(0xffffffffu, y[j], 2);
            y[j] += __shfl_xor_sync(0xffffffffu, y[j], 4);
            y[j] += __shfl_xor_sync(0xffffffffu, y[j], 8);
        }
        if (n == 0) {
#pragma unroll
            for (int j = 0; j < 8; j++)
                up[(size_t)(l + j) * DI] =
                    __float2bfloat16_rn(fmaf(xf[j], Dc, y[j]) * rf[j]);
        }
    }
}

// ---------------- launch ----------------------------------------------------
extern "C" void kernel_launch(void* const* d_in, const int* in_sizes, int n_in,
                              void* d_out, int out_size) {
    const float* x          = (const float*)d_in[0];
    const float* norm_scale = (const float*)d_in[1];
    const float* w_in       = (const float*)d_in[2];
    const float* conv_w     = (const float*)d_in[3];
    const float* conv_b     = (const float*)d_in[4];
    const float* A_log      = (const float*)d_in[5];
    const float* Dv         = (const float*)d_in[6];
    const float* w_xproj    = (const float*)d_in[7];
    const float* w_dt       = (const float*)d_in[8];
    const float* b_dt       = (const float*)d_in[9];
    const float* w_out      = (const float*)d_in[10];

    __nv_bfloat16 *hnormb, *hb, *xsb, *xsT, *resT, *deltaT, *ub;
    __nv_bfloat16 *w_inT, *w_outT, *w_xprojT;
    float *proj, *delta, *w_dtT;
    cudaGetSymbolAddress((void**)&hnormb, g_hnormb);
    cudaGetSymbolAddress((void**)&hb, g_hb);
    cudaGetSymbolAddress((void**)&xsb, g_xsb);
    cudaGetSymbolAddress((void**)&xsT, g_xsT);
    cudaGetSymbolAddress((void**)&resT, g_resT);
    cudaGetSymbolAddress((void**)&deltaT, g_deltaT);
    cudaGetSymbolAddress((void**)&proj, g_proj);
    cudaGetSymbolAddress((void**)&delta, g_delta);
    cudaGetSymbolAddress((void**)&ub, g_ub);
    cudaGetSymbolAddress((void**)&w_inT, g_w_inT);
    cudaGetSymbolAddress((void**)&w_outT, g_w_outT);
    cudaGetSymbolAddress((void**)&w_xprojT, g_w_xprojT);
    cudaGetSymbolAddress((void**)&w_dtT, g_w_dtT);

    dim3 t32x8(32, 8);
    // 0
    transpose_bf<<<dim3(DM / 32, 4 * DM / 32), t32x8>>>(w_in, w_inT, DM, 4 * DM, 4 * DM);
    // 1
    rmsnorm_k<<<LSEQ, 256>>>(x, norm_scale);
    // 2
    zero_proj_k<<<LSEQ * NPROJ / 4 / 256, 256>>>();
    // 3 (ncu capture slot): h = hnorm @ w_in, bf16 out
    bgemm<0><<<dim3(4 * DM / 128, LSEQ / 128), 256>>>(
        DM, DM, DM, 4 * DM, 4 * DM, hnormb, w_inT, nullptr, hb);
    // 4-6 weight transposes
    transpose_bf<<<dim3(DI / 32, DM / 32), t32x8>>>(w_out, w_outT, DI, DM, DM);
    transpose_bf<<<dim3(DI / 32, 128 / 32), t32x8>>>(w_xproj, w_xprojT, DI, NPROJ, 128);
    transpose_f32<<<dim3(DTR / 32, DI / 32), t32x8>>>(w_dt, w_dtT, DTR, DI);
    // 7: conv + silu -> xs (row-major bf16)
    conv_silu_k<<<LSEQ * DI / 256, 256>>>(conv_w, conv_b);
    // 8: res_T = silu(h[:, DI:])^T   9: xs_T = xs^T
    transpose_bb<1><<<dim3(LSEQ / 32, DI / 32), t32x8>>>(hb, resT, LSEQ, 4 * DM, DI);
    transpose_bb<0><<<dim3(LSEQ / 32, DI / 32), t32x8>>>(xsb, xsT, LSEQ, DI, 0);
    // 10: proj = xs @ w_xproj, split-K=8
    bgemm<3><<<dim3(1, LSEQ / 128, 8), 256>>>(
        DI / 8, DI, DI, NPROJ, NPROJ, xsb, w_xprojT, nullptr, proj);
    // 11: delta = softplus(proj[:, :64] @ w_dt + b_dt)  (tf32, fp32 row-major)
    mma_gemm_sp<<<dim3(DI / 128, LSEQ / 128), 256>>>(
        DTR, NPROJ, DTR, DI, proj, w_dtT, b_dt, delta);
    // 12: delta_T
    transpose_f2b<<<dim3(LSEQ / 32, DI / 32), t32x8>>>(delta, deltaT, LSEQ, DI);
    // 13: selective scan v2
    scan2_k<<<DI / 16, 256>>>(A_log, Dv);
    // 14: out = x + u @ w_out
    bgemm<2><<<dim3(DM / 128, LSEQ / 128), 256>>>(
        DI, DI, DI, DM, DM, ub, w_outT, x, (float*)d_out);
}

// round 16
// speedup vs baseline: 2.1420x; 1.0089x over previous
#include <cuda_runtime.h>
#include <cuda_bf16.h>
#include <cuda_fp16.h>
#include <cstdint>
#include <math.h>

#define LSEQ 2048
#define DM   1024
#define DI   2048
#define DTR  64
#define NS   16
#define NPROJ 96   // dt_rank + 2N

// ---------------- scratch (static device allocations; no cudaMalloc) --------
__device__ __nv_bfloat16 g_hnormb[LSEQ * DM];     // rmsnorm out (bf16)
__device__ __nv_bfloat16 g_hb[LSEQ * 4 * DM];     // in-proj out [xs|res] bf16
__device__ __nv_bfloat16 g_xsb[LSEQ * DI];        // silu(conv) bf16 row-major
__device__ __nv_bfloat16 g_xsT[DI * LSEQ];        // xs channel-major
__device__ __nv_bfloat16 g_resT[DI * LSEQ];       // silu(res) channel-major
__device__ float g_proj[LSEQ * NPROJ];            // [delta_low(64) | B(16) | C(16)]
__device__ float g_delta[LSEQ * DI];              // softplus out fp32 row-major
__device__ __nv_bfloat16 g_deltaT[DI * LSEQ];     // delta channel-major bf16
__device__ __nv_bfloat16 g_ub[LSEQ * DI];         // scan out bf16 row-major
// K-major weights
__device__ __nv_bfloat16 g_w_inT[4 * DM * DM];
__device__ __nv_bfloat16 g_w_outT[DM * DI];
__device__ __nv_bfloat16 g_w_xprojT[128 * DI];
__device__ float g_w_dtT[DI * DTR];

__device__ __forceinline__ float siluf(float x) {
    return x / (1.0f + __expf(-x));
}
__device__ __forceinline__ uint32_t tf32r(float x) {
    uint32_t y;
    asm("cvt.rna.tf32.f32 %0, %1;" : "=r"(y) : "f"(x));
    return y;
}
__device__ __forceinline__ uint32_t smem_u32(const void* p) {
    uint32_t a;
    asm("{ .reg .u64 t; cvta.to.shared.u64 t, %1; cvt.u32.u64 %0, t; }"
        : "=r"(a) : "l"(p));
    return a;
}
__device__ __forceinline__ void ldm_x4(uint32_t& r0, uint32_t& r1,
                                       uint32_t& r2, uint32_t& r3, uint32_t addr) {
    asm volatile("ldmatrix.sync.aligned.m8n8.x4.shared.b16 {%0,%1,%2,%3}, [%4];"
                 : "=r"(r0), "=r"(r1), "=r"(r2), "=r"(r3) : "r"(addr));
}
__device__ __forceinline__ float2 bf2_to_f2(uint32_t u) {
    __nv_bfloat162 b;
    memcpy(&b, &u, 4);
    return __bfloat1622float2(b);
}

// ============ bf16 HMMA GEMM: 128x128 tile, BK=32, 8 warps (2x4) ============
// R11/R15-proven structure: reg-staged double buffer + ldmatrix fragment loads.
// EPI 0: store bf16  2: fp32 acc + X[row,col]  3: atomicAdd fp32 cols < nstore
#define BSTH 40  // halfs per smem row (32 + 8 pad)

template <int EPI>
__global__ void __launch_bounds__(256)
bgemm(int K, int lda, int ldb, int ldc, int nstore,
      const __nv_bfloat16* __restrict__ A, const __nv_bfloat16* __restrict__ B,
      const float* __restrict__ X, void* __restrict__ Cout) {
    __shared__ __nv_bfloat16 As[2][128 * BSTH];
    __shared__ __nv_bfloat16 Bs[2][128 * BSTH];
    int tid = threadIdx.x;
    int wid = tid >> 5, lane = tid & 31;
    int wm = wid & 1;        // 2 warps over M (64 rows each)
    int wn = wid >> 1;       // 4 warps over N (32 cols each)
    int g = lane >> 2, tg = lane & 3;

    const __nv_bfloat16* Ab = A + (size_t)(blockIdx.y * 128) * lda + (size_t)blockIdx.z * K;
    const __nv_bfloat16* Bb = B + (size_t)(blockIdx.x * 128) * ldb + (size_t)blockIdx.z * K;

    float c[4][4][4];
#pragma unroll
    for (int i = 0; i < 4; i++)
#pragma unroll
        for (int j = 0; j < 4; j++)
#pragma unroll
            for (int k = 0; k < 4; k++) c[i][j][k] = 0.f;

    const int S = K / 32;
    int r = tid >> 1;            // 0..127
    int hb = (tid & 1) * 16;     // col-half (16 bf16 = 32B)

    uint32_t a_off = (((uint32_t)(wm * 64 + (lane & 15)) * BSTH) + 8u * (lane >> 4)) * 2u;
    uint32_t b_off = (((uint32_t)(wn * 32 + (lane & 7) + 8 * ((lane >> 3) >> 1)) * BSTH)
                      + 8u * ((lane >> 3) & 1)) * 2u;

    // prologue -> buf 0
    {
        const __nv_bfloat16* pa = Ab + (size_t)r * lda + hb;
        const __nv_bfloat16* pb = Bb + (size_t)r * ldb + hb;
        *(uint4*)&As[0][r * BSTH + hb]     = *(const uint4*)pa;
        *(uint4*)&As[0][r * BSTH + hb + 8] = *(const uint4*)(pa + 8);
        *(uint4*)&Bs[0][r * BSTH + hb]     = *(const uint4*)pb;
        *(uint4*)&Bs[0][r * BSTH + hb + 8] = *(const uint4*)(pb + 8);
    }
    __syncthreads();

    for (int s = 0; s < S; s++) {
        int buf = s & 1;
        uint4 va0, va1, vb0, vb1;
        const bool more = (s + 1) < S;
        if (more) {
            const __nv_bfloat16* pa = Ab + (size_t)r * lda + (s + 1) * 32 + hb;
            const __nv_bfloat16* pb = Bb + (size_t)r * ldb + (s + 1) * 32 + hb;
            va0 = *(const uint4*)pa;
            va1 = *(const uint4*)(pa + 8);
            vb0 = *(const uint4*)pb;
            vb1 = *(const uint4*)(pb + 8);
        }
        uint32_t sA = smem_u32(&As[buf][0]);
        uint32_t sB = smem_u32(&Bs[buf][0]);
#pragma unroll
        for (int kk = 0; kk < 32; kk += 16) {
            uint32_t af[4][4], bf[4][2];
#pragma unroll
            for (int mt = 0; mt < 4; mt++)
                ldm_x4(af[mt][0], af[mt][1], af[mt][2], af[mt][3],
                       sA + a_off + (uint32_t)(mt * 16 * BSTH + kk) * 2u);
#pragma unroll
            for (int p = 0; p < 2; p++)
                ldm_x4(bf[2 * p][0], bf[2 * p][1], bf[2 * p + 1][0], bf[2 * p + 1][1],
                       sB + b_off + (uint32_t)(p * 16 * BSTH + kk) * 2u);
#pragma unroll
            for (int mt = 0; mt < 4; mt++)
#pragma unroll
                for (int nt = 0; nt < 4; nt++) {
                    asm volatile(
                        "mma.sync.aligned.m16n8k16.row.col.f32.bf16.bf16.f32 "
                        "{%0,%1,%2,%3}, {%4,%5,%6,%7}, {%8,%9}, {%0,%1,%2,%3};"
                        : "+f"(c[mt][nt][0]), "+f"(c[mt][nt][1]),
                          "+f"(c[mt][nt][2]), "+f"(c[mt][nt][3])
                        : "r"(af[mt][0]), "r"(af[mt][1]), "r"(af[mt][2]), "r"(af[mt][3]),
                          "r"(bf[nt][0]), "r"(bf[nt][1]));
                }
        }
        if (more) {
            int nb = buf ^ 1;
            *(uint4*)&As[nb][r * BSTH + hb]     = va0;
            *(uint4*)&As[nb][r * BSTH + hb + 8] = va1;
            *(uint4*)&Bs[nb][r * BSTH + hb]     = vb0;
            *(uint4*)&Bs[nb][r * BSTH + hb + 8] = vb1;
        }
        __syncthreads();
    }

#pragma unroll
    for (int mt = 0; mt < 4; mt++) {
        int row = blockIdx.y * 128 + wm * 64 + mt * 16 + g;
#pragma unroll
        for (int nt = 0; nt < 4; nt++) {
            int col = blockIdx.x * 128 + wn * 32 + nt * 8 + tg * 2;
#pragma unroll
            for (int h = 0; h < 2; h++) {
                int rr = row + h * 8;
                float v0 = c[mt][nt][h * 2 + 0];
                float v1 = c[mt][nt][h * 2 + 1];
                if (EPI == 0) {
                    __nv_bfloat162 st;
                    st.x = __float2bfloat16_rn(v0);
                    st.y = __float2bfloat16_rn(v1);
                    *(__nv_bfloat162*)&((__nv_bfloat16*)Cout)[(size_t)rr * ldc + col] = st;
                } else if (EPI == 2) {
                    v0 += X[(size_t)rr * ldc + col];
                    v1 += X[(size_t)rr * ldc + col + 1];
                    *(float2*)&((float*)Cout)[(size_t)rr * ldc + col] = make_float2(v0, v1);
                } else {  // EPI == 3
                    if (col < nstore) {
                        atomicAdd(&((float*)Cout)[(size_t)rr * ldc + col], v0);
                        atomicAdd(&((float*)Cout)[(size_t)rr * ldc + col + 1], v1);
                    }
                }
            }
        }
    }
}

// ============ tf32 HMMA GEMM (delta path only), BK=16 =======================
#define BK 16
#define SST 20

__global__ void __launch_bounds__(256)
mma_gemm_sp(int K, int lda, int ldb, int ldc,
            const float* __restrict__ A, const float* __restrict__ B,
            const float* __restrict__ X, float* __restrict__ C) {
    __shared__ uint32_t As[2][128 * SST];
    __shared__ uint32_t Bs[2][128 * SST];
    int tid = threadIdx.x;
    int wid = tid >> 5, lane = tid & 31;
    int wm = wid & 1, wn = wid >> 1;
    int g = lane >> 2, tg = lane & 3;

    const float* Ab = A + (size_t)(blockIdx.y * 128) * lda;
    const float* Bb = B + (size_t)(blockIdx.x * 128) * ldb;

    float c[4][4][4];
#pragma unroll
    for (int i = 0; i < 4; i++)
#pragma unroll
        for (int j = 0; j < 4; j++)
#pragma unroll
            for (int k = 0; k < 4; k++) c[i][j][k] = 0.f;

    const int S = K / BK;
    int r0 = tid >> 2, kq0 = tid & 3;
    int r1 = (tid + 256) >> 2, kq1 = tid & 3;

    {
        float4 a0v = *(const float4*)(Ab + (size_t)r0 * lda + kq0 * 4);
        float4 a1v = *(const float4*)(Ab + (size_t)r1 * lda + kq1 * 4);
        float4 b0v = *(const float4*)(Bb + (size_t)r0 * ldb + kq0 * 4);
        float4 b1v = *(const float4*)(Bb + (size_t)r1 * ldb + kq1 * 4);
        *(uint4*)&As[0][r0 * SST + kq0 * 4] =
            make_uint4(tf32r(a0v.x), tf32r(a0v.y), tf32r(a0v.z), tf32r(a0v.w));
        *(uint4*)&As[0][r1 * SST + kq1 * 4] =
            make_uint4(tf32r(a1v.x), tf32r(a1v.y), tf32r(a1v.z), tf32r(a1v.w));
        *(uint4*)&Bs[0][r0 * SST + kq0 * 4] =
            make_uint4(tf32r(b0v.x), tf32r(b0v.y), tf32r(b0v.z), tf32r(b0v.w));
        *(uint4*)&Bs[0][r1 * SST + kq1 * 4] =
            make_uint4(tf32r(b1v.x), tf32r(b1v.y), tf32r(b1v.z), tf32r(b1v.w));
    }
    __syncthreads();

    for (int s = 0; s < S; s++) {
        int buf = s & 1;
        float4 a0v, a1v, b0v, b1v;
        const bool more = (s + 1) < S;
        if (more) {
            int k0 = (s + 1) * BK;
            a0v = *(const float4*)(Ab + (size_t)r0 * lda + k0 + kq0 * 4);
            a1v = *(const float4*)(Ab + (size_t)r1 * lda + k0 + kq1 * 4);
            b0v = *(const float4*)(Bb + (size_t)r0 * ldb + k0 + kq0 * 4);
            b1v = *(const float4*)(Bb + (size_t)r1 * ldb + k0 + kq1 * 4);
        }
#pragma unroll
        for (int kk = 0; kk < BK; kk += 8) {
            uint32_t af[4][4], bf[4][2];
#pragma unroll
            for (int mt = 0; mt < 4; mt++) {
                const uint32_t* p = &As[buf][(wm * 64 + mt * 16 + g) * SST + kk + tg];
                af[mt][0] = p[0];
                af[mt][1] = p[8 * SST];
                af[mt][2] = p[4];
                af[mt][3] = p[8 * SST + 4];
            }
#pragma unroll
            for (int nt = 0; nt < 4; nt++) {
                const uint32_t* q = &Bs[buf][(wn * 32 + nt * 8 + g) * SST + kk + tg];
                bf[nt][0] = q[0];
                bf[nt][1] = q[4];
            }
#pragma unroll
            for (int mt = 0; mt < 4; mt++)
#pragma unroll
                for (int nt = 0; nt < 4; nt++) {
                    asm volatile(
                        "mma.sync.aligned.m16n8k8.row.col.f32.tf32.tf32.f32 "
                        "{%0,%1,%2,%3}, {%4,%5,%6,%7}, {%8,%9}, {%0,%1,%2,%3};"
                        : "+f"(c[mt][nt][0]), "+f"(c[mt][nt][1]),
                          "+f"(c[mt][nt][2]), "+f"(c[mt][nt][3])
                        : "r"(af[mt][0]), "r"(af[mt][1]), "r"(af[mt][2]), "r"(af[mt][3]),
                          "r"(bf[nt][0]), "r"(bf[nt][1]));
                }
        }
        if (more) {
            int nb = buf ^ 1;
            *(uint4*)&As[nb][r0 * SST + kq0 * 4] =
                make_uint4(tf32r(a0v.x), tf32r(a0v.y), tf32r(a0v.z), tf32r(a0v.w));
            *(uint4*)&As[nb][r1 * SST + kq1 * 4] =
                make_uint4(tf32r(a1v.x), tf32r(a1v.y), tf32r(a1v.z), tf32r(a1v.w));
            *(uint4*)&Bs[nb][r0 * SST + kq0 * 4] =
                make_uint4(tf32r(b0v.x), tf32r(b0v.y), tf32r(b0v.z), tf32r(b0v.w));
            *(uint4*)&Bs[nb][r1 * SST + kq1 * 4] =
                make_uint4(tf32r(b1v.x), tf32r(b1v.y), tf32r(b1v.z), tf32r(b1v.w));
        }
        __syncthreads();
    }

    // epilogue: softplus(acc + bias[col])
#pragma unroll
    for (int mt = 0; mt < 4; mt++) {
        int row = blockIdx.y * 128 + wm * 64 + mt * 16 + g;
#pragma unroll
        for (int nt = 0; nt < 4; nt++) {
            int col = blockIdx.x * 128 + wn * 32 + nt * 8 + tg * 2;
#pragma unroll
            for (int h = 0; h < 2; h++) {
                int rr = row + h * 8;
                float v0 = c[mt][nt][h * 2 + 0] + X[col];
                float v1 = c[mt][nt][h * 2 + 1] + X[col + 1];
                v0 = (v0 > 20.f) ? v0 : log1pf(__expf(v0));
                v1 = (v1 > 20.f) ? v1 : log1pf(__expf(v1));
                *(float2*)&C[(size_t)rr * ldc + col] = make_float2(v0, v1);
            }
        }
    }
}

// ---------------- weight transposes ------------------------------------------
__global__ void transpose_bf(const float* __restrict__ in, __nv_bfloat16* __restrict__ out,
                             int K, int N, int NOUT) {
    __shared__ float t[32][33];
    int kb = blockIdx.x * 32, nb = blockIdx.y * 32;
    int tx = threadIdx.x, ty = threadIdx.y;  // 32 x 8
#pragma unroll
    for (int i = 0; i < 32; i += 8) {
        int k = kb + ty + i, n = nb + tx;
        t[ty + i][tx] = (n < N) ? in[(size_t)k * N + n] : 0.f;
    }
    __syncthreads();
#pragma unroll
    for (int i = 0; i < 32; i += 8) {
        int n = nb + ty + i, k = kb + tx;
        if (n < NOUT) out[(size_t)n * K + k] = __float2bfloat16_rn(t[tx][ty + i]);
    }
}
__global__ void transpose_f32(const float* __restrict__ in, float* __restrict__ out,
                              int K, int N) {
    __shared__ float t[32][33];
    int kb = blockIdx.x * 32, nb = blockIdx.y * 32;
    int tx = threadIdx.x, ty = threadIdx.y;
#pragma unroll
    for (int i = 0; i < 32; i += 8)
        t[ty + i][tx] = in[(size_t)(kb + ty + i) * N + nb + tx];
    __syncthreads();
#pragma unroll
    for (int i = 0; i < 32; i += 8)
        out[(size_t)(nb + ty + i) * K + kb + tx] = t[tx][ty + i];
}

// data transposes (row-major [R, Cld] slice -> channel-major [Csub, R] bf16)
template <int SILU>
__global__ void transpose_bb(const __nv_bfloat16* __restrict__ in,
                             __nv_bfloat16* __restrict__ out,
                             int R, int Cld, int c_off) {
    __shared__ float t[32][33];
    int rb = blockIdx.x * 32, cb = blockIdx.y * 32;
    int tx = threadIdx.x, ty = threadIdx.y;  // 32 x 8
#pragma unroll
    for (int i = 0; i < 32; i += 8) {
        float v = __bfloat162float(in[(size_t)(rb + ty + i) * Cld + c_off + cb + tx]);
        t[ty + i][tx] = SILU ? siluf(v) : v;
    }
    __syncthreads();
#pragma unroll
    for (int i = 0; i < 32; i += 8)
        out[(size_t)(cb + ty + i) * R + rb + tx] = __float2bfloat16_rn(t[tx][ty + i]);
}
__global__ void transpose_f2b(const float* __restrict__ in,
                              __nv_bfloat16* __restrict__ out, int R, int C) {
    __shared__ float t[32][33];
    int rb = blockIdx.x * 32, cb = blockIdx.y * 32;
    int tx = threadIdx.x, ty = threadIdx.y;
#pragma unroll
    for (int i = 0; i < 32; i += 8)
        t[ty + i][tx] = in[(size_t)(rb + ty + i) * C + cb + tx];
    __syncthreads();
#pragma unroll
    for (int i = 0; i < 32; i += 8)
        out[(size_t)(cb + ty + i) * R + rb + tx] = __float2bfloat16_rn(t[tx][ty + i]);
}

__global__ void zero_proj_k() {
    int i = blockIdx.x * 256 + threadIdx.x;
    ((float4*)g_proj)[i] = make_float4(0.f, 0.f, 0.f, 0.f);
}
// init d_out with residual x (split-K out-proj accumulates on top)
__global__ void copy_x_k(const float* __restrict__ x, float* __restrict__ out) {
    int i = blockIdx.x * 256 + threadIdx.x;
    ((float4*)out)[i] = ((const float4*)x)[i];
}

// ---------------- RMSNorm (writes bf16) -------------------------------------
__global__ void rmsnorm_k(const float* __restrict__ x,
                          const float* __restrict__ sc) {
    int row = blockIdx.x;
    int t = threadIdx.x;
    float4 v = ((const float4*)(x + (size_t)row * DM))[t];
    float s = v.x * v.x + v.y * v.y + v.z * v.z + v.w * v.w;
#pragma unroll
    for (int o = 16; o; o >>= 1) s += __shfl_xor_sync(0xffffffffu, s, o);
    __shared__ float red[8];
    if ((t & 31) == 0) red[t >> 5] = s;
    __syncthreads();
    float tot = 0.f;
#pragma unroll
    for (int i = 0; i < 8; i++) tot += red[i];
    float inv = rsqrtf(tot * (1.0f / DM) + 1e-5f);
    float4 gsc = ((const float4*)sc)[t];
    __nv_bfloat162 p0, p1;
    p0.x = __float2bfloat16_rn(v.x * inv * gsc.x);
    p0.y = __float2bfloat16_rn(v.y * inv * gsc.y);
    p1.x = __float2bfloat16_rn(v.z * inv * gsc.z);
    p1.y = __float2bfloat16_rn(v.w * inv * gsc.w);
    ((__nv_bfloat162*)(g_hnormb + (size_t)row * DM))[t * 2] = p0;
    ((__nv_bfloat162*)(g_hnormb + (size_t)row * DM))[t * 2 + 1] = p1;
}

// ---------------- causal depthwise conv (K=4) + silu (bf16 in/out) ----------
__global__ void conv_silu_k(const float* __restrict__ cw,
                            const float* __restrict__ cb) {
    int idx = blockIdx.x * 256 + threadIdx.x;
    int c = idx & (DI - 1);
    int l = idx >> 11;
    float acc = cb[c];
#pragma unroll
    for (int k = 0; k < 4; k++) {
        int ls = l - 3 + k;
        if (ls >= 0)
            acc = fmaf(__bfloat162float(g_hb[(size_t)ls * (4 * DM) + c]),
                       cw[k * DI + c], acc);
    }
    g_xsb[idx] = __float2bfloat16_rn(siluf(acc));
}

// ---------------- selective scan v2: channel-major broadcast loads ----------
__global__ void __launch_bounds__(256) scan2_k(const float* __restrict__ A_log,
                                               const float* __restrict__ Dp) {
    int lane = threadIdx.x & 31;
    int n = lane & 15;
    int half = lane >> 4;
    int warp = threadIdx.x >> 5;
    int c = blockIdx.x * 16 + warp * 2 + half;

    float Ah = -__expf(A_log[c * NS + n]) * 1.44269504f;  // log2(e) folded
    float Dc = Dp[c];
    float state = 0.f;

    const __nv_bfloat16* dT = g_deltaT + (size_t)c * LSEQ;
    const __nv_bfloat16* xT = g_xsT + (size_t)c * LSEQ;
    const __nv_bfloat16* rT = g_resT + (size_t)c * LSEQ;
    __nv_bfloat16* up = g_ub + c;

    for (int l = 0; l < LSEQ; l += 8) {
        uint4 dv = *(const uint4*)(dT + l);
        uint4 xv = *(const uint4*)(xT + l);
        uint4 rv = *(const uint4*)(rT + l);
        float d[8], xf[8], rf[8];
        {
            float2 f;
            f = bf2_to_f2(dv.x); d[0] = f.x; d[1] = f.y;
            f = bf2_to_f2(dv.y); d[2] = f.x; d[3] = f.y;
            f = bf2_to_f2(dv.z); d[4] = f.x; d[5] = f.y;
            f = bf2_to_f2(dv.w); d[6] = f.x; d[7] = f.y;
            f = bf2_to_f2(xv.x); xf[0] = f.x; xf[1] = f.y;
            f = bf2_to_f2(xv.y); xf[2] = f.x; xf[3] = f.y;
            f = bf2_to_f2(xv.z); xf[4] = f.x; xf[5] = f.y;
            f = bf2_to_f2(xv.w); xf[6] = f.x; xf[7] = f.y;
            f = bf2_to_f2(rv.x); rf[0] = f.x; rf[1] = f.y;
            f = bf2_to_f2(rv.y); rf[2] = f.x; rf[3] = f.y;
            f = bf2_to_f2(rv.z); rf[4] = f.x; rf[5] = f.y;
            f = bf2_to_f2(rv.w); rf[6] = f.x; rf[7] = f.y;
        }
        float Bv[8], Cv[8];
#pragma unroll
        for (int j = 0; j < 8; j++) {
            Bv[j] = g_proj[(size_t)(l + j) * NPROJ + DTR + n];
            Cv[j] = g_proj[(size_t)(l + j) * NPROJ + DTR + NS + n];
        }
        float dA[8];
#pragma unroll
        for (int j = 0; j < 8; j += 2) {
            __half2 hh = h2exp2(__floats2half2_rn(d[j] * Ah, d[j + 1] * Ah));
            dA[j] = __low2float(hh);
            dA[j + 1] = __high2float(hh);
        }
        float y[8];
#pragma unroll
        for (int j = 0; j < 8; j++) {
            state = fmaf(dA[j], state, d[j] * xf[j] * Bv[j]);
            y[j] = state * Cv[j];
        }
#pragma unroll
        for (int j = 0; j < 8; j++) {
            y[j] += __shfl_xor_sync(0xffffffffu, y[j], 1);
            y[j] += __shfl_xor_sync(0xffffffffu, y[j], 2);
            y[j] += __shfl_xor_sync(0xffffffffu, y[j], 4);
            y[j] += __shfl_xor_sync(0xffffffffu, y[j], 8);
        }
        if (n == 0) {
#pragma unroll
            for (int j = 0; j < 8; j++)
                up[(size_t)(l + j) * DI] =
                    __float2bfloat16_rn(fmaf(xf[j], Dc, y[j]) * rf[j]);
        }
    }
}

// ---------------- launch ----------------------------------------------------
extern "C" void kernel_launch(void* const* d_in, const int* in_sizes, int n_in,
                              void* d_out, int out_size) {
    const float* x          = (const float*)d_in[0];
    const float* norm_scale = (const float*)d_in[1];
    const float* w_in       = (const float*)d_in[2];
    const float* conv_w     = (const float*)d_in[3];
    const float* conv_b     = (const float*)d_in[4];
    const float* A_log      = (const float*)d_in[5];
    const float* Dv         = (const float*)d_in[6];
    const float* w_xproj    = (const float*)d_in[7];
    const float* w_dt       = (const float*)d_in[8];
    const float* b_dt       = (const float*)d_in[9];
    const float* w_out      = (const float*)d_in[10];

    __nv_bfloat16 *hnormb, *hb, *xsb, *xsT, *resT, *deltaT, *ub;
    __nv_bfloat16 *w_inT, *w_outT, *w_xprojT;
    float *proj, *delta, *w_dtT;
    cudaGetSymbolAddress((void**)&hnormb, g_hnormb);
    cudaGetSymbolAddress((void**)&hb, g_hb);
    cudaGetSymbolAddress((void**)&xsb, g_xsb);
    cudaGetSymbolAddress((void**)&xsT, g_xsT);
    cudaGetSymbolAddress((void**)&resT, g_resT);
    cudaGetSymbolAddress((void**)&deltaT, g_deltaT);
    cudaGetSymbolAddress((void**)&proj, g_proj);
    cudaGetSymbolAddress((void**)&delta, g_delta);
    cudaGetSymbolAddress((void**)&ub, g_ub);
    cudaGetSymbolAddress((void**)&w_inT, g_w_inT);
    cudaGetSymbolAddress((void**)&w_outT, g_w_outT);
    cudaGetSymbolAddress((void**)&w_xprojT, g_w_xprojT);
    cudaGetSymbolAddress((void**)&w_dtT, g_w_dtT);

    dim3 t32x8(32, 8);
    // 0
    transpose_bf<<<dim3(DM / 32, 4 * DM / 32), t32x8>>>(w_in, w_inT, DM, 4 * DM, 4 * DM);
    // 1
    rmsnorm_k<<<LSEQ, 256>>>(x, norm_scale);
    // 2
    zero_proj_k<<<LSEQ * NPROJ / 4 / 256, 256>>>();
    // 3 (ncu capture slot): h = hnorm @ w_in, bf16 out
    bgemm<0><<<dim3(4 * DM / 128, LSEQ / 128), 256>>>(
        DM, DM, DM, 4 * DM, 4 * DM, hnormb, w_inT, nullptr, hb);
    // 4: init d_out with residual x
    copy_x_k<<<LSEQ * DM / 4 / 256, 256>>>(x, (float*)d_out);
    // 5-7 weight transposes
    transpose_bf<<<dim3(DI / 32, DM / 32), t32x8>>>(w_out, w_outT, DI, DM, DM);
    transpose_bf<<<dim3(DI / 32, 128 / 32), t32x8>>>(w_xproj, w_xprojT, DI, NPROJ, 128);
    transpose_f32<<<dim3(DTR / 32, DI / 32), t32x8>>>(w_dt, w_dtT, DTR, DI);
    // 8: conv + silu -> xs (row-major bf16)
    conv_silu_k<<<LSEQ * DI / 256, 256>>>(conv_w, conv_b);
    // 9: res_T = silu(h[:, DI:])^T   10: xs_T = xs^T
    transpose_bb<1><<<dim3(LSEQ / 32, DI / 32), t32x8>>>(hb, resT, LSEQ, 4 * DM, DI);
    transpose_bb<0><<<dim3(LSEQ / 32, DI / 32), t32x8>>>(xsb, xsT, LSEQ, DI, 0);
    // 11: proj = xs @ w_xproj, split-K=8
    bgemm<3><<<dim3(1, LSEQ / 128, 8), 256>>>(
        DI / 8, DI, DI, NPROJ, NPROJ, xsb, w_xprojT, nullptr, proj);
    // 12: delta = softplus(proj[:, :64] @ w_dt + b_dt)  (tf32, fp32 row-major)
    mma_gemm_sp<<<dim3(DI / 128, LSEQ / 128), 256>>>(
        DTR, NPROJ, DTR, DI, proj, w_dtT, b_dt, delta);
    // 13: delta_T
    transpose_f2b<<<dim3(LSEQ / 32, DI / 32), t32x8>>>(delta, deltaT, LSEQ, DI);
    // 14: selective scan v2
    scan2_k<<<DI / 16, 256>>>(A_log, Dv);
    // 15: out += u @ w_out  (split-K=2, 256 CTAs)
    bgemm<3><<<dim3(DM / 128, LSEQ / 128, 2), 256>>>(
        DI / 2, DI, DI, DM, DM, ub, w_outT, nullptr, (float*)d_out);
}

// round 17
// speedup vs baseline: 2.8749x; 1.3422x over previous
#include <cuda_runtime.h>
#include <cuda_bf16.h>
#include <cuda_fp16.h>
#include <cstdint>
#include <math.h>

#define LSEQ 2048
#define DM   1024
#define DI   2048
#define DTR  64
#define NS   16
#define NPROJ 96   // dt_rank + 2N

// ---------------- scratch (static device allocations; no cudaMalloc) --------
__device__ __nv_bfloat16 g_hnormb[LSEQ * DM];     // rmsnorm out (bf16)
__device__ __nv_bfloat16 g_hb[LSEQ * 4 * DM];     // in-proj out [xs|res] bf16
__device__ __nv_bfloat16 g_xsb[LSEQ * DI];        // silu(conv) bf16 row-major
__device__ __nv_bfloat16 g_xsT[DI * LSEQ];        // xs channel-major
__device__ __nv_bfloat16 g_resT[DI * LSEQ];       // silu(res) channel-major
__device__ float g_proj[LSEQ * NPROJ];            // [delta_low(64) | B(16) | C(16)]
__device__ float g_delta[LSEQ * DI];              // softplus out fp32 row-major
__device__ __nv_bfloat16 g_deltaT[DI * LSEQ];     // delta channel-major bf16
__device__ __nv_bfloat16 g_ub[LSEQ * DI];         // scan out bf16 row-major
// K-major weights
__device__ __nv_bfloat16 g_w_inT[4 * DM * DM];
__device__ __nv_bfloat16 g_w_outT[DM * DI];
__device__ __nv_bfloat16 g_w_xprojT[128 * DI];
__device__ float g_w_dtT[DI * DTR];

__device__ __forceinline__ float siluf(float x) {
    return x / (1.0f + __expf(-x));
}
__device__ __forceinline__ uint32_t tf32r(float x) {
    uint32_t y;
    asm("cvt.rna.tf32.f32 %0, %1;" : "=r"(y) : "f"(x));
    return y;
}
__device__ __forceinline__ uint32_t smem_u32(const void* p) {
    uint32_t a;
    asm("{ .reg .u64 t; cvta.to.shared.u64 t, %1; cvt.u32.u64 %0, t; }"
        : "=r"(a) : "l"(p));
    return a;
}
__device__ __forceinline__ void ldm_x4(uint32_t& r0, uint32_t& r1,
                                       uint32_t& r2, uint32_t& r3, uint32_t addr) {
    asm volatile("ldmatrix.sync.aligned.m8n8.x4.shared.b16 {%0,%1,%2,%3}, [%4];"
                 : "=r"(r0), "=r"(r1), "=r"(r2), "=r"(r3) : "r"(addr));
}
__device__ __forceinline__ float2 bf2_to_f2(uint32_t u) {
    __nv_bfloat162 b;
    memcpy(&b, &u, 4);
    return __bfloat1622float2(b);
}

// ============ bf16 HMMA GEMM: 128x128 tile, BK=32, 8 warps (2x4) ============
// R11/R15-proven structure: reg-staged double buffer + ldmatrix fragment loads.
// EPI 0: store bf16  2: fp32 acc + X[row,col]  3: atomicAdd fp32 cols < nstore
#define BSTH 40  // halfs per smem row (32 + 8 pad)

template <int EPI>
__global__ void __launch_bounds__(256)
bgemm(int K, int lda, int ldb, int ldc, int nstore,
      const __nv_bfloat16* __restrict__ A, const __nv_bfloat16* __restrict__ B,
      const float* __restrict__ X, void* __restrict__ Cout) {
    __shared__ __nv_bfloat16 As[2][128 * BSTH];
    __shared__ __nv_bfloat16 Bs[2][128 * BSTH];
    int tid = threadIdx.x;
    int wid = tid >> 5, lane = tid & 31;
    int wm = wid & 1;        // 2 warps over M (64 rows each)
    int wn = wid >> 1;       // 4 warps over N (32 cols each)
    int g = lane >> 2, tg = lane & 3;

    const __nv_bfloat16* Ab = A + (size_t)(blockIdx.y * 128) * lda + (size_t)blockIdx.z * K;
    const __nv_bfloat16* Bb = B + (size_t)(blockIdx.x * 128) * ldb + (size_t)blockIdx.z * K;

    float c[4][4][4];
#pragma unroll
    for (int i = 0; i < 4; i++)
#pragma unroll
        for (int j = 0; j < 4; j++)
#pragma unroll
            for (int k = 0; k < 4; k++) c[i][j][k] = 0.f;

    const int S = K / 32;
    int r = tid >> 1;            // 0..127
    int hb = (tid & 1) * 16;     // col-half (16 bf16 = 32B)

    uint32_t a_off = (((uint32_t)(wm * 64 + (lane & 15)) * BSTH) + 8u * (lane >> 4)) * 2u;
    uint32_t b_off = (((uint32_t)(wn * 32 + (lane & 7) + 8 * ((lane >> 3) >> 1)) * BSTH)
                      + 8u * ((lane >> 3) & 1)) * 2u;

    // prologue -> buf 0
    {
        const __nv_bfloat16* pa = Ab + (size_t)r * lda + hb;
        const __nv_bfloat16* pb = Bb + (size_t)r * ldb + hb;
        *(uint4*)&As[0][r * BSTH + hb]     = *(const uint4*)pa;
        *(uint4*)&As[0][r * BSTH + hb + 8] = *(const uint4*)(pa + 8);
        *(uint4*)&Bs[0][r * BSTH + hb]     = *(const uint4*)pb;
        *(uint4*)&Bs[0][r * BSTH + hb + 8] = *(const uint4*)(pb + 8);
    }
    __syncthreads();

    for (int s = 0; s < S; s++) {
        int buf = s & 1;
        uint4 va0, va1, vb0, vb1;
        const bool more = (s + 1) < S;
        if (more) {
            const __nv_bfloat16* pa = Ab + (size_t)r * lda + (s + 1) * 32 + hb;
            const __nv_bfloat16* pb = Bb + (size_t)r * ldb + (s + 1) * 32 + hb;
            va0 = *(const uint4*)pa;
            va1 = *(const uint4*)(pa + 8);
            vb0 = *(const uint4*)pb;
            vb1 = *(const uint4*)(pb + 8);
        }
        uint32_t sA = smem_u32(&As[buf][0]);
        uint32_t sB = smem_u32(&Bs[buf][0]);
#pragma unroll
        for (int kk = 0; kk < 32; kk += 16) {
            uint32_t af[4][4], bf[4][2];
#pragma unroll
            for (int mt = 0; mt < 4; mt++)
                ldm_x4(af[mt][0], af[mt][1], af[mt][2], af[mt][3],
                       sA + a_off + (uint32_t)(mt * 16 * BSTH + kk) * 2u);
#pragma unroll
            for (int p = 0; p < 2; p++)
                ldm_x4(bf[2 * p][0], bf[2 * p][1], bf[2 * p + 1][0], bf[2 * p + 1][1],
                       sB + b_off + (uint32_t)(p * 16 * BSTH + kk) * 2u);
#pragma unroll
            for (int mt = 0; mt < 4; mt++)
#pragma unroll
                for (int nt = 0; nt < 4; nt++) {
                    asm volatile(
                        "mma.sync.aligned.m16n8k16.row.col.f32.bf16.bf16.f32 "
                        "{%0,%1,%2,%3}, {%4,%5,%6,%7}, {%8,%9}, {%0,%1,%2,%3};"
                        : "+f"(c[mt][nt][0]), "+f"(c[mt][nt][1]),
                          "+f"(c[mt][nt][2]), "+f"(c[mt][nt][3])
                        : "r"(af[mt][0]), "r"(af[mt][1]), "r"(af[mt][2]), "r"(af[mt][3]),
                          "r"(bf[nt][0]), "r"(bf[nt][1]));
                }
        }
        if (more) {
            int nb = buf ^ 1;
            *(uint4*)&As[nb][r * BSTH + hb]     = va0;
            *(uint4*)&As[nb][r * BSTH + hb + 8] = va1;
            *(uint4*)&Bs[nb][r * BSTH + hb]     = vb0;
            *(uint4*)&Bs[nb][r * BSTH + hb + 8] = vb1;
        }
        __syncthreads();
    }

#pragma unroll
    for (int mt = 0; mt < 4; mt++) {
        int row = blockIdx.y * 128 + wm * 64 + mt * 16 + g;
#pragma unroll
        for (int nt = 0; nt < 4; nt++) {
            int col = blockIdx.x * 128 + wn * 32 + nt * 8 + tg * 2;
#pragma unroll
            for (int h = 0; h < 2; h++) {
                int rr = row + h * 8;
                float v0 = c[mt][nt][h * 2 + 0];
                float v1 = c[mt][nt][h * 2 + 1];
                if (EPI == 0) {
                    __nv_bfloat162 st;
                    st.x = __float2bfloat16_rn(v0);
                    st.y = __float2bfloat16_rn(v1);
                    *(__nv_bfloat162*)&((__nv_bfloat16*)Cout)[(size_t)rr * ldc + col] = st;
                } else if (EPI == 2) {
                    v0 += X[(size_t)rr * ldc + col];
                    v1 += X[(size_t)rr * ldc + col + 1];
                    *(float2*)&((float*)Cout)[(size_t)rr * ldc + col] = make_float2(v0, v1);
                } else {  // EPI == 3
                    if (col < nstore) {
                        atomicAdd(&((float*)Cout)[(size_t)rr * ldc + col], v0);
                        atomicAdd(&((float*)Cout)[(size_t)rr * ldc + col + 1], v1);
                    }
                }
            }
        }
    }
}

// ============ tf32 HMMA GEMM (delta path only), BK=16 =======================
#define BK 16
#define SST 20

__global__ void __launch_bounds__(256)
mma_gemm_sp(int K, int lda, int ldb, int ldc,
            const float* __restrict__ A, const float* __restrict__ B,
            const float* __restrict__ X, float* __restrict__ C) {
    __shared__ uint32_t As[2][128 * SST];
    __shared__ uint32_t Bs[2][128 * SST];
    int tid = threadIdx.x;
    int wid = tid >> 5, lane = tid & 31;
    int wm = wid & 1, wn = wid >> 1;
    int g = lane >> 2, tg = lane & 3;

    const float* Ab = A + (size_t)(blockIdx.y * 128) * lda;
    const float* Bb = B + (size_t)(blockIdx.x * 128) * ldb;

    float c[4][4][4];
#pragma unroll
    for (int i = 0; i < 4; i++)
#pragma unroll
        for (int j = 0; j < 4; j++)
#pragma unroll
            for (int k = 0; k < 4; k++) c[i][j][k] = 0.f;

    const int S = K / BK;
    int r0 = tid >> 2, kq0 = tid & 3;
    int r1 = (tid + 256) >> 2, kq1 = tid & 3;

    {
        float4 a0v = *(const float4*)(Ab + (size_t)r0 * lda + kq0 * 4);
        float4 a1v = *(const float4*)(Ab + (size_t)r1 * lda + kq1 * 4);
        float4 b0v = *(const float4*)(Bb + (size_t)r0 * ldb + kq0 * 4);
        float4 b1v = *(const float4*)(Bb + (size_t)r1 * ldb + kq1 * 4);
        *(uint4*)&As[0][r0 * SST + kq0 * 4] =
            make_uint4(tf32r(a0v.x), tf32r(a0v.y), tf32r(a0v.z), tf32r(a0v.w));
        *(uint4*)&As[0][r1 * SST + kq1 * 4] =
            make_uint4(tf32r(a1v.x), tf32r(a1v.y), tf32r(a1v.z), tf32r(a1v.w));
        *(uint4*)&Bs[0][r0 * SST + kq0 * 4] =
            make_uint4(tf32r(b0v.x), tf32r(b0v.y), tf32r(b0v.z), tf32r(b0v.w));
        *(uint4*)&Bs[0][r1 * SST + kq1 * 4] =
            make_uint4(tf32r(b1v.x), tf32r(b1v.y), tf32r(b1v.z), tf32r(b1v.w));
    }
    __syncthreads();

    for (int s = 0; s < S; s++) {
        int buf = s & 1;
        float4 a0v, a1v, b0v, b1v;
        const bool more = (s + 1) < S;
        if (more) {
            int k0 = (s + 1) * BK;
            a0v = *(const float4*)(Ab + (size_t)r0 * lda + k0 + kq0 * 4);
            a1v = *(const float4*)(Ab + (size_t)r1 * lda + k0 + kq1 * 4);
            b0v = *(const float4*)(Bb + (size_t)r0 * ldb + k0 + kq0 * 4);
            b1v = *(const float4*)(Bb + (size_t)r1 * ldb + k0 + kq1 * 4);
        }
#pragma unroll
        for (int kk = 0; kk < BK; kk += 8) {
            uint32_t af[4][4], bf[4][2];
#pragma unroll
            for (int mt = 0; mt < 4; mt++) {
                const uint32_t* p = &As[buf][(wm * 64 + mt * 16 + g) * SST + kk + tg];
                af[mt][0] = p[0];
                af[mt][1] = p[8 * SST];
                af[mt][2] = p[4];
                af[mt][3] = p[8 * SST + 4];
            }
#pragma unroll
            for (int nt = 0; nt < 4; nt++) {
                const uint32_t* q = &Bs[buf][(wn * 32 + nt * 8 + g) * SST + kk + tg];
                bf[nt][0] = q[0];
                bf[nt][1] = q[4];
            }
#pragma unroll
            for (int mt = 0; mt < 4; mt++)
#pragma unroll
                for (int nt = 0; nt < 4; nt++) {
                    asm volatile(
                        "mma.sync.aligned.m16n8k8.row.col.f32.tf32.tf32.f32 "
                        "{%0,%1,%2,%3}, {%4,%5,%6,%7}, {%8,%9}, {%0,%1,%2,%3};"
                        : "+f"(c[mt][nt][0]), "+f"(c[mt][nt][1]),
                          "+f"(c[mt][nt][2]), "+f"(c[mt][nt][3])
                        : "r"(af[mt][0]), "r"(af[mt][1]), "r"(af[mt][2]), "r"(af[mt][3]),
                          "r"(bf[nt][0]), "r"(bf[nt][1]));
                }
        }
        if (more) {
            int nb = buf ^ 1;
            *(uint4*)&As[nb][r0 * SST + kq0 * 4] =
                make_uint4(tf32r(a0v.x), tf32r(a0v.y), tf32r(a0v.z), tf32r(a0v.w));
            *(uint4*)&As[nb][r1 * SST + kq1 * 4] =
                make_uint4(tf32r(a1v.x), tf32r(a1v.y), tf32r(a1v.z), tf32r(a1v.w));
            *(uint4*)&Bs[nb][r0 * SST + kq0 * 4] =
                make_uint4(tf32r(b0v.x), tf32r(b0v.y), tf32r(b0v.z), tf32r(b0v.w));
            *(uint4*)&Bs[nb][r1 * SST + kq1 * 4] =
                make_uint4(tf32r(b1v.x), tf32r(b1v.y), tf32r(b1v.z), tf32r(b1v.w));
        }
        __syncthreads();
    }

    // epilogue: softplus(acc + bias[col]) — fast-math log/exp
#pragma unroll
    for (int mt = 0; mt < 4; mt++) {
        int row = blockIdx.y * 128 + wm * 64 + mt * 16 + g;
#pragma unroll
        for (int nt = 0; nt < 4; nt++) {
            int col = blockIdx.x * 128 + wn * 32 + nt * 8 + tg * 2;
#pragma unroll
            for (int h = 0; h < 2; h++) {
                int rr = row + h * 8;
                float v0 = c[mt][nt][h * 2 + 0] + X[col];
                float v1 = c[mt][nt][h * 2 + 1] + X[col + 1];
                v0 = (v0 > 20.f) ? v0 : __logf(1.f + __expf(v0));
                v1 = (v1 > 20.f) ? v1 : __logf(1.f + __expf(v1));
                *(float2*)&C[(size_t)rr * ldc + col] = make_float2(v0, v1);
            }
        }
    }
}

// ---------------- weight transposes ------------------------------------------
__global__ void transpose_bf(const float* __restrict__ in, __nv_bfloat16* __restrict__ out,
                             int K, int N, int NOUT) {
    __shared__ float t[32][33];
    int kb = blockIdx.x * 32, nb = blockIdx.y * 32;
    int tx = threadIdx.x, ty = threadIdx.y;  // 32 x 8
#pragma unroll
    for (int i = 0; i < 32; i += 8) {
        int k = kb + ty + i, n = nb + tx;
        t[ty + i][tx] = (n < N) ? in[(size_t)k * N + n] : 0.f;
    }
    __syncthreads();
#pragma unroll
    for (int i = 0; i < 32; i += 8) {
        int n = nb + ty + i, k = kb + tx;
        if (n < NOUT) out[(size_t)n * K + k] = __float2bfloat16_rn(t[tx][ty + i]);
    }
}
__global__ void transpose_f32(const float* __restrict__ in, float* __restrict__ out,
                              int K, int N) {
    __shared__ float t[32][33];
    int kb = blockIdx.x * 32, nb = blockIdx.y * 32;
    int tx = threadIdx.x, ty = threadIdx.y;
#pragma unroll
    for (int i = 0; i < 32; i += 8)
        t[ty + i][tx] = in[(size_t)(kb + ty + i) * N + nb + tx];
    __syncthreads();
#pragma unroll
    for (int i = 0; i < 32; i += 8)
        out[(size_t)(nb + ty + i) * K + kb + tx] = t[tx][ty + i];
}

// data transposes (row-major [R, Cld] slice -> channel-major [Csub, R] bf16)
template <int SILU>
__global__ void transpose_bb(const __nv_bfloat16* __restrict__ in,
                             __nv_bfloat16* __restrict__ out,
                             int R, int Cld, int c_off) {
    __shared__ float t[32][33];
    int rb = blockIdx.x * 32, cb = blockIdx.y * 32;
    int tx = threadIdx.x, ty = threadIdx.y;  // 32 x 8
#pragma unroll
    for (int i = 0; i < 32; i += 8) {
        float v = __bfloat162float(in[(size_t)(rb + ty + i) * Cld + c_off + cb + tx]);
        t[ty + i][tx] = SILU ? siluf(v) : v;
    }
    __syncthreads();
#pragma unroll
    for (int i = 0; i < 32; i += 8)
        out[(size_t)(cb + ty + i) * R + rb + tx] = __float2bfloat16_rn(t[tx][ty + i]);
}
__global__ void transpose_f2b(const float* __restrict__ in,
                              __nv_bfloat16* __restrict__ out, int R, int C) {
    __shared__ float t[32][33];
    int rb = blockIdx.x * 32, cb = blockIdx.y * 32;
    int tx = threadIdx.x, ty = threadIdx.y;
#pragma unroll
    for (int i = 0; i < 32; i += 8)
        t[ty + i][tx] = in[(size_t)(rb + ty + i) * C + cb + tx];
    __syncthreads();
#pragma unroll
    for (int i = 0; i < 32; i += 8)
        out[(size_t)(cb + ty + i) * R + rb + tx] = __float2bfloat16_rn(t[tx][ty + i]);
}

__global__ void zero_proj_k() {
    int i = blockIdx.x * 256 + threadIdx.x;
    ((float4*)g_proj)[i] = make_float4(0.f, 0.f, 0.f, 0.f);
}
// init d_out with residual x (split-K out-proj accumulates on top)
__global__ void copy_x_k(const float* __restrict__ x, float* __restrict__ out) {
    int i = blockIdx.x * 256 + threadIdx.x;
    ((float4*)out)[i] = ((const float4*)x)[i];
}

// ---------------- RMSNorm (writes bf16) -------------------------------------
__global__ void rmsnorm_k(const float* __restrict__ x,
                          const float* __restrict__ sc) {
    int row = blockIdx.x;
    int t = threadIdx.x;
    float4 v = ((const float4*)(x + (size_t)row * DM))[t];
    float s = v.x * v.x + v.y * v.y + v.z * v.z + v.w * v.w;
#pragma unroll
    for (int o = 16; o; o >>= 1) s += __shfl_xor_sync(0xffffffffu, s, o);
    __shared__ float red[8];
    if ((t & 31) == 0) red[t >> 5] = s;
    __syncthreads();
    float tot = 0.f;
#pragma unroll
    for (int i = 0; i < 8; i++) tot += red[i];
    float inv = rsqrtf(tot * (1.0f / DM) + 1e-5f);
    float4 gsc = ((const float4*)sc)[t];
    __nv_bfloat162 p0, p1;
    p0.x = __float2bfloat16_rn(v.x * inv * gsc.x);
    p0.y = __float2bfloat16_rn(v.y * inv * gsc.y);
    p1.x = __float2bfloat16_rn(v.z * inv * gsc.z);
    p1.y = __float2bfloat16_rn(v.w * inv * gsc.w);
    ((__nv_bfloat162*)(g_hnormb + (size_t)row * DM))[t * 2] = p0;
    ((__nv_bfloat162*)(g_hnormb + (size_t)row * DM))[t * 2 + 1] = p1;
}

// ---------------- causal depthwise conv (K=4) + silu (bf16 in/out) ----------
__global__ void conv_silu_k(const float* __restrict__ cw,
                            const float* __restrict__ cb) {
    int idx = blockIdx.x * 256 + threadIdx.x;
    int c = idx & (DI - 1);
    int l = idx >> 11;
    float acc = cb[c];
#pragma unroll
    for (int k = 0; k < 4; k++) {
        int ls = l - 3 + k;
        if (ls >= 0)
            acc = fmaf(__bfloat162float(g_hb[(size_t)ls * (4 * DM) + c]),
                       cw[k * DI + c], acc);
    }
    g_xsb[idx] = __float2bfloat16_rn(siluf(acc));
}

// ---------------- selective scan v3: smem-staged B/C, 256 CTAs --------------
// 128 threads = 4 warps = 8 channels per CTA; grid = DI/8 = 256 CTAs.
// B/C staged per 128-step chunk into smem (coalesced), read via LDS broadcast.
#define SCHUNK 128

__global__ void __launch_bounds__(128) scan3_k(const float* __restrict__ A_log,
                                               const float* __restrict__ Dp) {
    __shared__ float sbc[SCHUNK * 32];   // [step][B(16) | C(16)]
    int tid = threadIdx.x;
    int lane = tid & 31;
    int n = lane & 15;
    int half = lane >> 4;
    int warp = tid >> 5;
    int c = blockIdx.x * 8 + warp * 2 + half;

    float Ah = -__expf(A_log[c * NS + n]) * 1.44269504f;  // log2(e) folded
    float Dc = Dp[c];
    float state = 0.f;

    const __nv_bfloat16* dT = g_deltaT + (size_t)c * LSEQ;
    const __nv_bfloat16* xT = g_xsT + (size_t)c * LSEQ;
    const __nv_bfloat16* rT = g_resT + (size_t)c * LSEQ;
    __nv_bfloat16* up = g_ub + c;

    for (int l0 = 0; l0 < LSEQ; l0 += SCHUNK) {
        // stage B/C chunk: 128 steps x 32 floats = 1024 float4 / 128 threads = 8 each
        __syncthreads();   // previous chunk fully consumed before overwrite
#pragma unroll
        for (int k = 0; k < 8; k++) {
            int idx4 = tid + k * 128;        // 0..1023
            int i = idx4 >> 3;               // step 0..127
            int jq = idx4 & 7;               // float4 index 0..7
            *(float4*)&sbc[i * 32 + jq * 4] =
                *(const float4*)&g_proj[(size_t)(l0 + i) * NPROJ + DTR + jq * 4];
        }
        __syncthreads();

        for (int li = 0; li < SCHUNK; li += 8) {
            int l = l0 + li;
            uint4 dv = *(const uint4*)(dT + l);
            uint4 xv = *(const uint4*)(xT + l);
            uint4 rv = *(const uint4*)(rT + l);
            float d[8], xf[8], rf[8];
            {
                float2 f;
                f = bf2_to_f2(dv.x); d[0] = f.x; d[1] = f.y;
                f = bf2_to_f2(dv.y); d[2] = f.x; d[3] = f.y;
                f = bf2_to_f2(dv.z); d[4] = f.x; d[5] = f.y;
                f = bf2_to_f2(dv.w); d[6] = f.x; d[7] = f.y;
                f = bf2_to_f2(xv.x); xf[0] = f.x; xf[1] = f.y;
                f = bf2_to_f2(xv.y); xf[2] = f.x; xf[3] = f.y;
                f = bf2_to_f2(xv.z); xf[4] = f.x; xf[5] = f.y;
                f = bf2_to_f2(xv.w); xf[6] = f.x; xf[7] = f.y;
                f = bf2_to_f2(rv.x); rf[0] = f.x; rf[1] = f.y;
                f = bf2_to_f2(rv.y); rf[2] = f.x; rf[3] = f.y;
                f = bf2_to_f2(rv.z); rf[4] = f.x; rf[5] = f.y;
                f = bf2_to_f2(rv.w); rf[6] = f.x; rf[7] = f.y;
            }
            float Bv[8], Cv[8];
#pragma unroll
            for (int j = 0; j < 8; j++) {
                Bv[j] = sbc[(li + j) * 32 + n];
                Cv[j] = sbc[(li + j) * 32 + 16 + n];
            }
            float dA[8];
#pragma unroll
            for (int j = 0; j < 8; j += 2) {
                __half2 hh = h2exp2(__floats2half2_rn(d[j] * Ah, d[j + 1] * Ah));
                dA[j] = __low2float(hh);
                dA[j + 1] = __high2float(hh);
            }
            float y[8];
#pragma unroll
            for (int j = 0; j < 8; j++) {
                state = fmaf(dA[j], state, d[j] * xf[j] * Bv[j]);
                y[j] = state * Cv[j];
            }
#pragma unroll
            for (int j = 0; j < 8; j++) {
                y[j] += __shfl_xor_sync(0xffffffffu, y[j], 1);
                y[j] += __shfl_xor_sync(0xffffffffu, y[j], 2);
                y[j] += __shfl_xor_sync(0xffffffffu, y[j], 4);
                y[j] += __shfl_xor_sync(0xffffffffu, y[j], 8);
            }
            if (n == 0) {
#pragma unroll
                for (int j = 0; j < 8; j++)
                    up[(size_t)(l + j) * DI] =
                        __float2bfloat16_rn(fmaf(xf[j], Dc, y[j]) * rf[j]);
            }
        }
    }
}

// ---------------- launch ----------------------------------------------------
extern "C" void kernel_launch(void* const* d_in, const int* in_sizes, int n_in,
                              void* d_out, int out_size) {
    const float* x          = (const float*)d_in[0];
    const float* norm_scale = (const float*)d_in[1];
    const float* w_in       = (const float*)d_in[2];
    const float* conv_w     = (const float*)d_in[3];
    const float* conv_b     = (const float*)d_in[4];
    const float* A_log      = (const float*)d_in[5];
    const float* Dv         = (const float*)d_in[6];
    const float* w_xproj    = (const float*)d_in[7];
    const float* w_dt       = (const float*)d_in[8];
    const float* b_dt       = (const float*)d_in[9];
    const float* w_out      = (const float*)d_in[10];

    __nv_bfloat16 *hnormb, *hb, *xsb, *xsT, *resT, *deltaT, *ub;
    __nv_bfloat16 *w_inT, *w_outT, *w_xprojT;
    float *proj, *delta, *w_dtT;
    cudaGetSymbolAddress((void**)&hnormb, g_hnormb);
    cudaGetSymbolAddress((void**)&hb, g_hb);
    cudaGetSymbolAddress((void**)&xsb, g_xsb);
    cudaGetSymbolAddress((void**)&xsT, g_xsT);
    cudaGetSymbolAddress((void**)&resT, g_resT);
    cudaGetSymbolAddress((void**)&deltaT, g_deltaT);
    cudaGetSymbolAddress((void**)&proj, g_proj);
    cudaGetSymbolAddress((void**)&delta, g_delta);
    cudaGetSymbolAddress((void**)&ub, g_ub);
    cudaGetSymbolAddress((void**)&w_inT, g_w_inT);
    cudaGetSymbolAddress((void**)&w_outT, g_w_outT);
    cudaGetSymbolAddress((void**)&w_xprojT, g_w_xprojT);
    cudaGetSymbolAddress((void**)&w_dtT, g_w_dtT);

    dim3 t32x8(32, 8);
    // 0
    transpose_bf<<<dim3(DM / 32, 4 * DM / 32), t32x8>>>(w_in, w_inT, DM, 4 * DM, 4 * DM);
    // 1
    rmsnorm_k<<<LSEQ, 256>>>(x, norm_scale);
    // 2
    zero_proj_k<<<LSEQ * NPROJ / 4 / 256, 256>>>();
    // 3 (ncu capture slot): h = hnorm @ w_in, bf16 out
    bgemm<0><<<dim3(4 * DM / 128, LSEQ / 128), 256>>>(
        DM, DM, DM, 4 * DM, 4 * DM, hnormb, w_inT, nullptr, hb);
    // 4: init d_out with residual x
    copy_x_k<<<LSEQ * DM / 4 / 256, 256>>>(x, (float*)d_out);
    // 5-7 weight transposes
    transpose_bf<<<dim3(DI / 32, DM / 32), t32x8>>>(w_out, w_outT, DI, DM, DM);
    transpose_bf<<<dim3(DI / 32, 128 / 32), t32x8>>>(w_xproj, w_xprojT, DI, NPROJ, 128);
    transpose_f32<<<dim3(DTR / 32, DI / 32), t32x8>>>(w_dt, w_dtT, DTR, DI);
    // 8: conv + silu -> xs (row-major bf16)
    conv_silu_k<<<LSEQ * DI / 256, 256>>>(conv_w, conv_b);
    // 9: res_T = silu(h[:, DI:])^T   10: xs_T = xs^T
    transpose_bb<1><<<dim3(LSEQ / 32, DI / 32), t32x8>>>(hb, resT, LSEQ, 4 * DM, DI);
    transpose_bb<0><<<dim3(LSEQ / 32, DI / 32), t32x8>>>(xsb, xsT, LSEQ, DI, 0);
    // 11: proj = xs @ w_xproj, split-K=8
    bgemm<3><<<dim3(1, LSEQ / 128, 8), 256>>>(
        DI / 8, DI, DI, NPROJ, NPROJ, xsb, w_xprojT, nullptr, proj);
    // 12: delta = softplus(proj[:, :64] @ w_dt + b_dt)  (tf32, fp32 row-major)
    mma_gemm_sp<<<dim3(DI / 128, LSEQ / 128), 256>>>(
        DTR, NPROJ, DTR, DI, proj, w_dtT, b_dt, delta);
    // 13: delta_T
    transpose_f2b<<<dim3(LSEQ / 32, DI / 32), t32x8>>>(delta, deltaT, LSEQ, DI);
    // 14: selective scan v3
    scan3_k<<<DI / 8, 128>>>(A_log, Dv);
    // 15: out += u @ w_out  (split-K=2, 256 CTAs)
    bgemm<3><<<dim3(DM / 128, LSEQ / 128, 2), 256>>>(
        DI / 2, DI, DI, DM, DM, ub, w_outT, nullptr, (float*)d_out);
}